// round 11
// baseline (speedup 1.0000x reference)
#include <cuda_runtime.h>
#include <cuda_bf16.h>
#include <math.h>

#define PAD 8192
#define B 32
#define K 32
#define L 128
#define H1 512
#define H2 64
#define BAGS 4
#define NT 512
#define XS 516          // float stride per poi bag (2064B, 16B multiple)
#define HS 68           // multiple of 4 -> float4-safe
#define NQBLK 32
#define NPBLK 256
#define NBLK (NQBLK + NPBLK)

__device__ float g_qsw[B * L];
__device__ float g_ts[B * K];
__device__ int   g_qflag[B];
__device__ int   g_bcnt[B];

__device__ __forceinline__ float prelu(float x, float a) {
    return x >= 0.f ? x : a * x;
}

__global__ __launch_bounds__(NT, 2)
void urban_kernel(const int* __restrict__ qbf,
                  const int* __restrict__ pbf,
                  const float* __restrict__ qloc,
                  const float* __restrict__ ploc,
                  const float* __restrict__ cw,
                  const float* __restrict__ qW1, const float* __restrict__ qb1,
                  const float* __restrict__ qW2, const float* __restrict__ qb2,
                  const float* __restrict__ pW1, const float* __restrict__ pb1,
                  const float* __restrict__ pW2, const float* __restrict__ pb2,
                  const float* __restrict__ qew, const float* __restrict__ pew,
                  const float* __restrict__ qa0p, const float* __restrict__ qa1p,
                  const float* __restrict__ qa2p, const float* __restrict__ pa0p,
                  const float* __restrict__ pa1p, const float* __restrict__ pa2p,
                  const float* __restrict__ indap,
                  const float* __restrict__ ap, const float* __restrict__ bp,
                  const float* __restrict__ cp, const float* __restrict__ dp,
                  float* __restrict__ out) {
    __shared__ __align__(16) int qidx[L];
    __shared__ __align__(16) int pidx[BAGS * L];
    __shared__ unsigned bitmap[BAGS * 256];
    __shared__ __align__(16) float x[BAGS * XS];
    __shared__ __align__(16) float qx[H1];
    __shared__ float    mp[8 * 256];
    __shared__ float    qpart[8 * 64];
    __shared__ __align__(16) float h1s[BAGS * HS];
    __shared__ __align__(16) float phs[BAGS * HS];
    __shared__ float    qh1[H2];
    __shared__ __align__(16) float qh[H2];
    __shared__ float    qsw[L];
    __shared__ float    wpart[16];
    __shared__ int      s_is_last;

    const int tid = threadIdx.x;
    const int bid = blockIdx.x;

    if (bid < NQBLK) {
        // ================= QUERY BLOCK: one b =================
        const int b = bid;
        const float a0 = *qa0p, a1 = *qa1p, a2 = *qa2p;
        const float ind_a = *indap;

        // gather: one column per thread; indices via broadcast __ldg int4
        {
            const int c = tid;
            const int4* idx4 = (const int4*)(qbf + (size_t)b * L);
            float accA = 0.f, accB = 0.f;
            bool all_ok = true;
#pragma unroll 4
            for (int l4 = 0; l4 < 32; l4++) {
                int4 v = __ldg(idx4 + l4);
                all_ok &= (v.x != PAD) & (v.y != PAD) & (v.z != PAD) & (v.w != PAD);
                float r0 = __ldg(cw + (size_t)v.x * H1 + c);
                float r1 = __ldg(cw + (size_t)v.y * H1 + c);
                float r2 = __ldg(cw + (size_t)v.z * H1 + c);
                float r3 = __ldg(cw + (size_t)v.w * H1 + c);
                accA += r0 + r1;
                accB += r2 + r3;
            }
            // stash qidx for the qsw phase (covered by next barrier)
            if (tid < L) qidx[tid] = __ldg(qbf + (size_t)b * L + tid);
            if (all_ok) {
                qx[c] = prelu((accA + accB) * (1.f / (float)L), a0);
            } else {
                // correctness fallback (PAD present): masked re-scan
                float acc = 0.f;
                int cnt = 0;
                for (int l = 0; l < L; l++) {
                    int v = __ldg(qbf + (size_t)b * L + l);
                    bool ok = (v != PAD);
                    cnt += ok;
                    acc = fmaf(ok ? 1.f : 0.f, __ldg(cw + (size_t)v * H1 + c), acc);
                }
                float inv = cnt > 0 ? 1.f / (float)cnt : 0.f;
                qx[c] = prelu(acc * inv, a0);
            }
        }
        __syncthreads();

        // MLP1: thread = (j, dp), 8 d-parts of 64; float4 LDS
        {
            int j = tid & 63, dpp = tid >> 6;
            const float* w = qW1 + (size_t)(dpp * 64) * H2 + j;
            const float4* xq4 = (const float4*)(&qx[dpp * 64]);
            float acc = 0.f;
#pragma unroll 4
            for (int d4 = 0; d4 < 16; d4++) {
                float4 xv = xq4[d4];
                acc = fmaf(xv.x, __ldg(w + (d4 * 4 + 0) * H2), acc);
                acc = fmaf(xv.y, __ldg(w + (d4 * 4 + 1) * H2), acc);
                acc = fmaf(xv.z, __ldg(w + (d4 * 4 + 2) * H2), acc);
                acc = fmaf(xv.w, __ldg(w + (d4 * 4 + 3) * H2), acc);
            }
            qpart[dpp * 64 + j] = acc;
        }
        __syncthreads();
        if (tid < H2) {
            float acc = qb1[tid];
#pragma unroll
            for (int p = 0; p < 8; p++) acc += qpart[p * 64 + tid];
            qh1[tid] = prelu(acc, a1);
        }
        __syncthreads();
        if (tid < 256) {
            int j = tid & 63, dpp = tid >> 6;
            const float* w = qW2 + (size_t)(dpp * 16) * H2 + j;
            float acc = 0.f;
#pragma unroll
            for (int d = 0; d < 16; d++)
                acc = fmaf(qh1[dpp * 16 + d], __ldg(w + d * H2), acc);
            qpart[dpp * 64 + j] = acc;
        }
        __syncthreads();
        if (tid < H2) {
            float acc = qb2[tid] + qpart[tid] + qpart[64 + tid] +
                        qpart[128 + tid] + qpart[192 + tid];
            qh[tid] = prelu(acc, a2);
        }
        __syncthreads();

        if (tid < L) {
            int v = qidx[tid];
            float s = 0.f;
            if (v != PAD) {
                const float4* qr4 = (const float4*)(qew + (size_t)v * H2);
                const float4* qh4 = (const float4*)qh;
                float qd = 0.f;
#pragma unroll
                for (int h = 0; h < 16; h++) {
                    float4 r = __ldg(qr4 + h), q = qh4[h];
                    qd += r.x * q.x + r.y * q.y + r.z * q.z + r.w * q.w;
                }
                s = prelu(qd, ind_a) + 1.f;
            }
            __stcg(&g_qsw[b * L + tid], s);
        }
        __syncthreads();
        if (tid == 0) {
            __threadfence();
            atomicExch(&g_qflag[b], 1);
        }
    } else {
        // ================= POI BLOCK: 4 (b,k) pairs, same b =================
        const int pair0 = (bid - NQBLK) * BAGS;
        const int bb = pair0 >> 5;
        const float a0 = *pa0p, a1 = *pa1p, a2 = *pa2p;
        const float ind_a = *indap;

        // ---- gather with ZERO preceding barriers ----
        {
            const int g = tid >> 7, slot = tid & 127;
            const int4* idx4 = (const int4*)(pbf + (size_t)(pair0 + g) * L);
            const float4* cw4 = (const float4*)cw;
            float4 aA = make_float4(0.f, 0.f, 0.f, 0.f);
            float4 aB = make_float4(0.f, 0.f, 0.f, 0.f);
            bool all_ok = true;
#pragma unroll 4
            for (int l4 = 0; l4 < 32; l4++) {
                int4 v = __ldg(idx4 + l4);
                all_ok &= (v.x != PAD) & (v.y != PAD) & (v.z != PAD) & (v.w != PAD);
                float4 r0 = __ldg(cw4 + (size_t)v.x * 128 + slot);
                float4 r1 = __ldg(cw4 + (size_t)v.y * 128 + slot);
                float4 r2 = __ldg(cw4 + (size_t)v.z * 128 + slot);
                float4 r3 = __ldg(cw4 + (size_t)v.w * 128 + slot);
                aA.x += r0.x + r1.x; aA.y += r0.y + r1.y;
                aA.z += r0.z + r1.z; aA.w += r0.w + r1.w;
                aB.x += r2.x + r3.x; aB.y += r2.y + r3.y;
                aB.z += r2.z + r3.z; aB.w += r2.w + r3.w;
            }
            // parallel smem staging for later phases (covered by next barrier)
            pidx[tid] = __ldg(pbf + (size_t)pair0 * L + tid);
            if (tid < L) qidx[tid] = __ldg(qbf + (size_t)bb * L + tid);
            bitmap[tid] = 0u;
            bitmap[tid + 512] = 0u;

            if (all_ok) {
                const float inv = 1.f / (float)L;
                float4 o;
                o.x = prelu((aA.x + aB.x) * inv, a0);
                o.y = prelu((aA.y + aB.y) * inv, a0);
                o.z = prelu((aA.z + aB.z) * inv, a0);
                o.w = prelu((aA.w + aB.w) * inv, a0);
                *(float4*)(&x[g * XS] + slot * 4) = o;
            } else {
                // correctness fallback: masked re-scan with count
                float4 a = make_float4(0.f, 0.f, 0.f, 0.f);
                int cnt = 0;
                const int* ip = pbf + (size_t)(pair0 + g) * L;
                for (int l = 0; l < L; l++) {
                    int v = __ldg(ip + l);
                    bool ok = (v != PAD);
                    cnt += ok;
                    float m = ok ? 1.f : 0.f;
                    float4 r = __ldg(cw4 + (size_t)v * 128 + slot);
                    a.x = fmaf(m, r.x, a.x); a.y = fmaf(m, r.y, a.y);
                    a.z = fmaf(m, r.z, a.z); a.w = fmaf(m, r.w, a.w);
                }
                float inv = cnt > 0 ? 1.f / (float)cnt : 0.f;
                float4 o;
                o.x = prelu(a.x * inv, a0); o.y = prelu(a.y * inv, a0);
                o.z = prelu(a.z * inv, a0); o.w = prelu(a.w * inv, a0);
                *(float4*)(&x[g * XS] + slot * 4) = o;
            }
        }
        __syncthreads();

        // ---- bitmap build (same phase as MLP1) ----
        {
            int v = pidx[tid];
            if (v != PAD)
                atomicOr(&bitmap[(tid >> 7) * 256 + (v >> 5)], 1u << (v & 31));
        }
        // ---- MLP1: one W1 load feeds 4 bag-accumulators; float4 LDS ----
        {
            int j = tid & 63, dpp = tid >> 6;   // 8 d-parts of 64
            const float* w = pW1 + (size_t)(dpp * 64) * H2 + j;
            const float4* x0 = (const float4*)(&x[0 * XS + dpp * 64]);
            const float4* x1 = (const float4*)(&x[1 * XS + dpp * 64]);
            const float4* x2 = (const float4*)(&x[2 * XS + dpp * 64]);
            const float4* x3 = (const float4*)(&x[3 * XS + dpp * 64]);
            float f0 = 0.f, f1 = 0.f, f2 = 0.f, f3 = 0.f;
#pragma unroll 4
            for (int d4 = 0; d4 < 16; d4++) {
                float4 a = x0[d4], bv = x1[d4], cv = x2[d4], dv = x3[d4];
#pragma unroll
                for (int u = 0; u < 4; u++) {
                    float wv = __ldg(w + (d4 * 4 + u) * H2);
                    f0 = fmaf((&a.x)[u], wv, f0);
                    f1 = fmaf((&bv.x)[u], wv, f1);
                    f2 = fmaf((&cv.x)[u], wv, f2);
                    f3 = fmaf((&dv.x)[u], wv, f3);
                }
            }
            mp[dpp * 256 + j]       = f0;
            mp[dpp * 256 + 64 + j]  = f1;
            mp[dpp * 256 + 128 + j] = f2;
            mp[dpp * 256 + 192 + j] = f3;
        }
        __syncthreads();
        if (tid < 256) {
            int j = tid & 63, g = tid >> 6;
            float acc = pb1[j];
#pragma unroll
            for (int p = 0; p < 8; p++) acc += mp[p * 256 + g * 64 + j];
            h1s[g * HS + j] = prelu(acc, a1);
        }
        __syncthreads();
        // ---- MLP2: one W2 load feeds 4 bags; float4 LDS ----
        if (tid < 256) {
            int j = tid & 63, dpp = tid >> 6;   // 4 d-parts of 16
            const float* w = pW2 + (size_t)(dpp * 16) * H2 + j;
            const float4* h0 = (const float4*)(&h1s[0 * HS + dpp * 16]);
            const float4* h1 = (const float4*)(&h1s[1 * HS + dpp * 16]);
            const float4* h2 = (const float4*)(&h1s[2 * HS + dpp * 16]);
            const float4* h3 = (const float4*)(&h1s[3 * HS + dpp * 16]);
            float f0 = 0.f, f1 = 0.f, f2 = 0.f, f3 = 0.f;
#pragma unroll
            for (int d4 = 0; d4 < 4; d4++) {
                float4 a = h0[d4], bv = h1[d4], cv = h2[d4], dv = h3[d4];
#pragma unroll
                for (int u = 0; u < 4; u++) {
                    float wv = __ldg(w + (d4 * 4 + u) * H2);
                    f0 = fmaf((&a.x)[u], wv, f0);
                    f1 = fmaf((&bv.x)[u], wv, f1);
                    f2 = fmaf((&cv.x)[u], wv, f2);
                    f3 = fmaf((&dv.x)[u], wv, f3);
                }
            }
            mp[dpp * 256 + j]       = f0;
            mp[dpp * 256 + 64 + j]  = f1;
            mp[dpp * 256 + 128 + j] = f2;
            mp[dpp * 256 + 192 + j] = f3;
        }
        __syncthreads();
        if (tid < 256) {
            int j = tid & 63, g = tid >> 6;
            float acc = pb2[j] + mp[g * 64 + j] + mp[256 + g * 64 + j] +
                        mp[512 + g * 64 + j] + mp[768 + g * 64 + j];
            phs[g * HS + j] = prelu(acc, a2);
        }
        if (tid == 0) {
            while (((volatile int*)g_qflag)[bb] == 0) {}
            __threadfence();
        }
        __syncthreads();
        if (tid < L) qsw[tid] = __ldcg(&g_qsw[bb * L + tid]);
        __syncthreads();

        // ---- probe + p-side dot; warp-shuffle reduction ----
        {
            int g = tid >> 7, i = tid & 127;
            int v = qidx[i];
            float val = 0.f;
            if (v != PAD && (bitmap[g * 256 + (v >> 5)] >> (v & 31)) & 1u) {
                const float4* pr4 = (const float4*)(pew + (size_t)v * H2);
                const float4* ph4 = (const float4*)(&phs[g * HS]);
                float pd = 0.f;
#pragma unroll
                for (int h = 0; h < 16; h++) {
                    float4 r = __ldg(pr4 + h), p = ph4[h];
                    pd += r.x * p.x + r.y * p.y + r.z * p.z + r.w * p.w;
                }
                val = qsw[i] * (prelu(pd, ind_a) + 1.f);
            }
#pragma unroll
            for (int off = 16; off > 0; off >>= 1)
                val += __shfl_xor_sync(0xffffffffu, val, off);
            if ((tid & 31) == 0) wpart[tid >> 5] = val;
        }
        __syncthreads();
        if (tid < BAGS) {
            float s = wpart[tid * 4] + wpart[tid * 4 + 1] +
                      wpart[tid * 4 + 2] + wpart[tid * 4 + 3];
            __stcg(&g_ts[pair0 + tid], s);
        }

        // ---- per-b distributed epilogue: 8th block of this b finishes it ----
        if (tid == 0) {
            __threadfence();
            s_is_last = (atomicAdd(&g_bcnt[bb], 1) == 7);
        }
        __syncthreads();
        if (s_is_last) {
            if (tid < K) {
                float ts = __ldcg(&g_ts[bb * K + tid]);
                float m = ts;
#pragma unroll
                for (int off = 16; off > 0; off >>= 1)
                    m = fmaxf(m, __shfl_xor_sync(0xffffffffu, m, off));
                float tsn = (2.f * ts - m) / (m + 1e-6f);
                float dx = qloc[bb * 2]     - ploc[(bb * K + tid) * 2];
                float dy = qloc[bb * 2 + 1] - ploc[(bb * K + tid) * 2 + 1];
                float dist_sim = -logf(sqrtf(dx * dx + dy * dy) + 1.f);
                float A = *ap, Bc = *bp, C = *cp, D = *dp;
                float sig = 1.f / (1.f + expf(-(A * tsn + Bc)));
                out[bb * K + tid] = (C - sig) * (dist_sim - D);
            }
            if (tid == 0) {
                g_qflag[bb] = 0;
                __threadfence();
                atomicExch(&g_bcnt[bb], 0);
            }
        }
    }
}

// ---------------------------------------------------------------------------
extern "C" void kernel_launch(void* const* d_in, const int* in_sizes, int n_in,
                              void* d_out, int out_size) {
    const int*   qbf  = (const int*)d_in[0];
    const int*   pbf  = (const int*)d_in[1];
    const float* qloc = (const float*)d_in[2];
    const float* ploc = (const float*)d_in[3];
    const float* cw   = (const float*)d_in[4];
    const float* qW1  = (const float*)d_in[5];
    const float* qb1  = (const float*)d_in[6];
    const float* qW2  = (const float*)d_in[7];
    const float* qb2  = (const float*)d_in[8];
    const float* pW1  = (const float*)d_in[9];
    const float* pb1  = (const float*)d_in[10];
    const float* pW2  = (const float*)d_in[11];
    const float* pb2  = (const float*)d_in[12];
    const float* qew  = (const float*)d_in[13];
    const float* pew  = (const float*)d_in[14];
    const float* qa0  = (const float*)d_in[15];
    const float* qa1  = (const float*)d_in[16];
    const float* qa2  = (const float*)d_in[17];
    const float* pa0  = (const float*)d_in[18];
    const float* pa1  = (const float*)d_in[19];
    const float* pa2  = (const float*)d_in[20];
    const float* inda = (const float*)d_in[21];
    const float* a    = (const float*)d_in[22];
    const float* b    = (const float*)d_in[23];
    const float* c    = (const float*)d_in[24];
    const float* d    = (const float*)d_in[25];
    float* out = (float*)d_out;

    urban_kernel<<<NBLK, NT>>>(qbf, pbf, qloc, ploc, cw,
                               qW1, qb1, qW2, qb2,
                               pW1, pb1, pW2, pb2,
                               qew, pew,
                               qa0, qa1, qa2, pa0, pa1, pa2,
                               inda, a, b, c, d, out);
}

// round 12
// speedup vs baseline: 1.0175x; 1.0175x over previous
#include <cuda_runtime.h>
#include <cuda_bf16.h>
#include <math.h>

#define PAD 8192
#define B 32
#define K 32
#define L 128
#define H1 512
#define H2 64
#define BAGS 4
#define NT 512
#define XS 516          // float stride per poi bag (2064B, 16B multiple)
#define HS 68           // multiple of 4 -> float4-safe
#define NQBLK 32
#define NPBLK 256
#define NBLK (NQBLK + NPBLK)

__device__ float g_qsw[B * L];
__device__ float g_ts[B * K];
__device__ int   g_qflag[B];
__device__ int   g_bcnt[B];

__device__ __forceinline__ float prelu(float x, float a) {
    return x >= 0.f ? x : a * x;
}

__global__ __launch_bounds__(NT, 2)
void urban_kernel(const int* __restrict__ qbf,
                  const int* __restrict__ pbf,
                  const float* __restrict__ qloc,
                  const float* __restrict__ ploc,
                  const float* __restrict__ cw,
                  const float* __restrict__ qW1, const float* __restrict__ qb1,
                  const float* __restrict__ qW2, const float* __restrict__ qb2,
                  const float* __restrict__ pW1, const float* __restrict__ pb1,
                  const float* __restrict__ pW2, const float* __restrict__ pb2,
                  const float* __restrict__ qew, const float* __restrict__ pew,
                  const float* __restrict__ qa0p, const float* __restrict__ qa1p,
                  const float* __restrict__ qa2p, const float* __restrict__ pa0p,
                  const float* __restrict__ pa1p, const float* __restrict__ pa2p,
                  const float* __restrict__ indap,
                  const float* __restrict__ ap, const float* __restrict__ bp,
                  const float* __restrict__ cp, const float* __restrict__ dp,
                  float* __restrict__ out) {
    __shared__ __align__(16) int qidx[L];
    __shared__ __align__(16) int pidx[BAGS * L];
    __shared__ unsigned bitmap[BAGS * 256];
    __shared__ int      s_wcnt[16];
    __shared__ __align__(16) float x[BAGS * XS];
    __shared__ __align__(16) float qx[H1];
    __shared__ float    mp[8 * 256];
    __shared__ float    qpart[8 * 64];
    __shared__ __align__(16) float h1s[BAGS * HS];
    __shared__ __align__(16) float phs[BAGS * HS];
    __shared__ float    qh1[H2];
    __shared__ __align__(16) float qh[H2];
    __shared__ float    wpart[16];
    __shared__ int      s_is_last;

    const int tid = threadIdx.x;
    const int bid = blockIdx.x;

    if (bid < NQBLK) {
        // ================= QUERY BLOCK: one b =================
        const int b = bid;
        const float a0 = *qa0p, a1 = *qa1p, a2 = *qa2p;
        const float ind_a = *indap;

        if (tid < L) {
            int v = qbf[(size_t)b * L + tid];
            qidx[tid] = v;
            unsigned bal = __ballot_sync(0xffffffffu, v != PAD);
            if ((tid & 31) == 0) s_wcnt[tid >> 5] = __popc(bal);
        }
        __syncthreads();

        // gather: one column per thread; fast unmasked path when no PAD
        {
            const int c = tid;
            const int cnt = s_wcnt[0] + s_wcnt[1] + s_wcnt[2] + s_wcnt[3];
            float accA = 0.f, accB = 0.f;
            if (cnt == L) {
#pragma unroll 4
                for (int l4 = 0; l4 < 32; l4++) {
                    int4 v = ((const int4*)qidx)[l4];
                    float r0 = __ldg(cw + (size_t)v.x * H1 + c);
                    float r1 = __ldg(cw + (size_t)v.y * H1 + c);
                    float r2 = __ldg(cw + (size_t)v.z * H1 + c);
                    float r3 = __ldg(cw + (size_t)v.w * H1 + c);
                    accA += r0 + r1;
                    accB += r2 + r3;
                }
                qx[c] = prelu((accA + accB) * (1.f / (float)L), a0);
            } else {
#pragma unroll 4
                for (int l = 0; l < L; l++) {
                    int v = qidx[l];
                    float m = (v != PAD) ? 1.f : 0.f;
                    accA = fmaf(m, __ldg(cw + (size_t)v * H1 + c), accA);
                }
                float inv = cnt > 0 ? 1.f / (float)cnt : 0.f;
                qx[c] = prelu(accA * inv, a0);
            }
        }
        __syncthreads();

        // MLP1: thread = (j, dp), 8 d-parts of 64; float4 LDS
        {
            int j = tid & 63, dpp = tid >> 6;
            const float* w = qW1 + (size_t)(dpp * 64) * H2 + j;
            const float4* xq4 = (const float4*)(&qx[dpp * 64]);
            float acc = 0.f;
#pragma unroll 4
            for (int d4 = 0; d4 < 16; d4++) {
                float4 xv = xq4[d4];
                acc = fmaf(xv.x, __ldg(w + (d4 * 4 + 0) * H2), acc);
                acc = fmaf(xv.y, __ldg(w + (d4 * 4 + 1) * H2), acc);
                acc = fmaf(xv.z, __ldg(w + (d4 * 4 + 2) * H2), acc);
                acc = fmaf(xv.w, __ldg(w + (d4 * 4 + 3) * H2), acc);
            }
            qpart[dpp * 64 + j] = acc;
        }
        __syncthreads();
        if (tid < H2) {
            float acc = qb1[tid];
#pragma unroll
            for (int p = 0; p < 8; p++) acc += qpart[p * 64 + tid];
            qh1[tid] = prelu(acc, a1);
        }
        __syncthreads();
        if (tid < 256) {
            int j = tid & 63, dpp = tid >> 6;
            const float* w = qW2 + (size_t)(dpp * 16) * H2 + j;
            float acc = 0.f;
#pragma unroll
            for (int d = 0; d < 16; d++)
                acc = fmaf(qh1[dpp * 16 + d], __ldg(w + d * H2), acc);
            qpart[dpp * 64 + j] = acc;
        }
        __syncthreads();
        if (tid < H2) {
            float acc = qb2[tid] + qpart[tid] + qpart[64 + tid] +
                        qpart[128 + tid] + qpart[192 + tid];
            qh[tid] = prelu(acc, a2);
        }
        __syncthreads();

        if (tid < L) {
            int v = qidx[tid];
            float s = 0.f;
            if (v != PAD) {
                const float4* qr4 = (const float4*)(qew + (size_t)v * H2);
                const float4* qh4 = (const float4*)qh;
                float qd = 0.f;
#pragma unroll
                for (int h = 0; h < 16; h++) {
                    float4 r = __ldg(qr4 + h), q = qh4[h];
                    qd += r.x * q.x + r.y * q.y + r.z * q.z + r.w * q.w;
                }
                s = prelu(qd, ind_a) + 1.f;
            }
            __stcg(&g_qsw[b * L + tid], s);
        }
        __syncthreads();
        if (tid == 0) {
            __threadfence();
            atomicExch(&g_qflag[b], 1);
        }
    } else {
        // ================= POI BLOCK: 4 (b,k) pairs, same b =================
        const int pair0 = (bid - NQBLK) * BAGS;
        const int bb = pair0 >> 5;
        const float a0 = *pa0p, a1 = *pa1p, a2 = *pa2p;
        const float ind_a = *indap;

        {
            int v = pbf[(size_t)pair0 * L + tid];
            pidx[tid] = v;
            unsigned bal = __ballot_sync(0xffffffffu, v != PAD);
            if ((tid & 31) == 0) s_wcnt[tid >> 5] = __popc(bal);
        }
        if (tid < L) qidx[tid] = qbf[(size_t)bb * L + tid];
        {
            bitmap[tid] = 0u;
            bitmap[tid + 512] = 0u;
        }
        __syncthreads();

        // ---- gather: 4 bags x 128 float4 slots; fast unmasked path ----
        {
            const int g = tid >> 7, slot = tid & 127;
            const int* ip = &pidx[g * L];
            const float4* cw4 = (const float4*)cw;
            float4 aA = make_float4(0.f, 0.f, 0.f, 0.f);
            float4 aB = make_float4(0.f, 0.f, 0.f, 0.f);
            const int cnt = s_wcnt[g * 4] + s_wcnt[g * 4 + 1] +
                            s_wcnt[g * 4 + 2] + s_wcnt[g * 4 + 3];
            if (cnt == L) {
#pragma unroll 4
                for (int l4 = 0; l4 < 32; l4++) {
                    int4 v = ((const int4*)ip)[l4];
                    float4 r0 = __ldg(cw4 + (size_t)v.x * 128 + slot);
                    float4 r1 = __ldg(cw4 + (size_t)v.y * 128 + slot);
                    float4 r2 = __ldg(cw4 + (size_t)v.z * 128 + slot);
                    float4 r3 = __ldg(cw4 + (size_t)v.w * 128 + slot);
                    aA.x += r0.x + r1.x; aA.y += r0.y + r1.y;
                    aA.z += r0.z + r1.z; aA.w += r0.w + r1.w;
                    aB.x += r2.x + r3.x; aB.y += r2.y + r3.y;
                    aB.z += r2.z + r3.z; aB.w += r2.w + r3.w;
                }
                const float inv = 1.f / (float)L;
                float4 o;
                o.x = prelu((aA.x + aB.x) * inv, a0);
                o.y = prelu((aA.y + aB.y) * inv, a0);
                o.z = prelu((aA.z + aB.z) * inv, a0);
                o.w = prelu((aA.w + aB.w) * inv, a0);
                *(float4*)(&x[g * XS] + slot * 4) = o;
            } else {
#pragma unroll 4
                for (int l = 0; l < L; l++) {
                    int v = ip[l];
                    float m = (v != PAD) ? 1.f : 0.f;
                    float4 r = __ldg(cw4 + (size_t)v * 128 + slot);
                    aA.x = fmaf(m, r.x, aA.x); aA.y = fmaf(m, r.y, aA.y);
                    aA.z = fmaf(m, r.z, aA.z); aA.w = fmaf(m, r.w, aA.w);
                }
                float inv = cnt > 0 ? 1.f / (float)cnt : 0.f;
                float4 o;
                o.x = prelu(aA.x * inv, a0); o.y = prelu(aA.y * inv, a0);
                o.z = prelu(aA.z * inv, a0); o.w = prelu(aA.w * inv, a0);
                *(float4*)(&x[g * XS] + slot * 4) = o;
            }
        }
        __syncthreads();

        // ---- bitmap build (same phase as MLP1) ----
        {
            int v = pidx[tid];
            if (v != PAD)
                atomicOr(&bitmap[(tid >> 7) * 256 + (v >> 5)], 1u << (v & 31));
        }
        // ---- MLP1: one W1 load feeds 4 bag-accumulators; float4 LDS ----
        {
            int j = tid & 63, dpp = tid >> 6;   // 8 d-parts of 64
            const float* w = pW1 + (size_t)(dpp * 64) * H2 + j;
            const float4* x0 = (const float4*)(&x[0 * XS + dpp * 64]);
            const float4* x1 = (const float4*)(&x[1 * XS + dpp * 64]);
            const float4* x2 = (const float4*)(&x[2 * XS + dpp * 64]);
            const float4* x3 = (const float4*)(&x[3 * XS + dpp * 64]);
            float f0 = 0.f, f1 = 0.f, f2 = 0.f, f3 = 0.f;
#pragma unroll 4
            for (int d4 = 0; d4 < 16; d4++) {
                float4 a = x0[d4], bv = x1[d4], cv = x2[d4], dv = x3[d4];
#pragma unroll
                for (int u = 0; u < 4; u++) {
                    float wv = __ldg(w + (d4 * 4 + u) * H2);
                    f0 = fmaf((&a.x)[u], wv, f0);
                    f1 = fmaf((&bv.x)[u], wv, f1);
                    f2 = fmaf((&cv.x)[u], wv, f2);
                    f3 = fmaf((&dv.x)[u], wv, f3);
                }
            }
            mp[dpp * 256 + j]       = f0;
            mp[dpp * 256 + 64 + j]  = f1;
            mp[dpp * 256 + 128 + j] = f2;
            mp[dpp * 256 + 192 + j] = f3;
        }
        __syncthreads();
        if (tid < 256) {
            int j = tid & 63, g = tid >> 6;
            float acc = pb1[j];
#pragma unroll
            for (int p = 0; p < 8; p++) acc += mp[p * 256 + g * 64 + j];
            h1s[g * HS + j] = prelu(acc, a1);
        }
        __syncthreads();
        // ---- MLP2: one W2 load feeds 4 bags; float4 LDS ----
        if (tid < 256) {
            int j = tid & 63, dpp = tid >> 6;   // 4 d-parts of 16
            const float* w = pW2 + (size_t)(dpp * 16) * H2 + j;
            const float4* h0 = (const float4*)(&h1s[0 * HS + dpp * 16]);
            const float4* h1 = (const float4*)(&h1s[1 * HS + dpp * 16]);
            const float4* h2 = (const float4*)(&h1s[2 * HS + dpp * 16]);
            const float4* h3 = (const float4*)(&h1s[3 * HS + dpp * 16]);
            float f0 = 0.f, f1 = 0.f, f2 = 0.f, f3 = 0.f;
#pragma unroll
            for (int d4 = 0; d4 < 4; d4++) {
                float4 a = h0[d4], bv = h1[d4], cv = h2[d4], dv = h3[d4];
#pragma unroll
                for (int u = 0; u < 4; u++) {
                    float wv = __ldg(w + (d4 * 4 + u) * H2);
                    f0 = fmaf((&a.x)[u], wv, f0);
                    f1 = fmaf((&bv.x)[u], wv, f1);
                    f2 = fmaf((&cv.x)[u], wv, f2);
                    f3 = fmaf((&dv.x)[u], wv, f3);
                }
            }
            mp[dpp * 256 + j]       = f0;
            mp[dpp * 256 + 64 + j]  = f1;
            mp[dpp * 256 + 128 + j] = f2;
            mp[dpp * 256 + 192 + j] = f3;
        }
        __syncthreads();
        if (tid < 256) {
            int j = tid & 63, g = tid >> 6;
            float acc = pb2[j] + mp[g * 64 + j] + mp[256 + g * 64 + j] +
                        mp[512 + g * 64 + j] + mp[768 + g * 64 + j];
            phs[g * HS + j] = prelu(acc, a2);
        }
        if (tid == 0) {
            while (((volatile int*)g_qflag)[bb] == 0) {}
            __threadfence();
        }
        __syncthreads();

        // ---- probe + p-side dot; qsw read direct from L2 (no staging) ----
        {
            int g = tid >> 7, i = tid & 127;
            int v = qidx[i];
            float val = 0.f;
            bool hit = (v != PAD) &&
                       ((bitmap[g * 256 + (v >> 5)] >> (v & 31)) & 1u);
            float qs = __ldcg(&g_qsw[bb * L + i]);   // issued early, used late
            if (hit) {
                const float4* pr4 = (const float4*)(pew + (size_t)v * H2);
                const float4* ph4 = (const float4*)(&phs[g * HS]);
                float pd = 0.f;
#pragma unroll
                for (int h = 0; h < 16; h++) {
                    float4 r = __ldg(pr4 + h), p = ph4[h];
                    pd += r.x * p.x + r.y * p.y + r.z * p.z + r.w * p.w;
                }
                val = qs * (prelu(pd, ind_a) + 1.f);
            }
#pragma unroll
            for (int off = 16; off > 0; off >>= 1)
                val += __shfl_xor_sync(0xffffffffu, val, off);
            if ((tid & 31) == 0) wpart[tid >> 5] = val;
        }
        __syncthreads();
        if (tid < BAGS) {
            float s = wpart[tid * 4] + wpart[tid * 4 + 1] +
                      wpart[tid * 4 + 2] + wpart[tid * 4 + 3];
            __stcg(&g_ts[pair0 + tid], s);
        }

        // ---- per-b distributed epilogue: 8th block of this b finishes it ----
        if (tid == 0) {
            __threadfence();
            s_is_last = (atomicAdd(&g_bcnt[bb], 1) == 7);
        }
        __syncthreads();
        if (s_is_last) {
            if (tid < K) {
                float ts = __ldcg(&g_ts[bb * K + tid]);
                float m = ts;
#pragma unroll
                for (int off = 16; off > 0; off >>= 1)
                    m = fmaxf(m, __shfl_xor_sync(0xffffffffu, m, off));
                float tsn = (2.f * ts - m) / (m + 1e-6f);
                float2 pl = __ldg((const float2*)(ploc + (size_t)(bb * K + tid) * 2));
                float dx = qloc[bb * 2]     - pl.x;
                float dy = qloc[bb * 2 + 1] - pl.y;
                float dist_sim = -logf(sqrtf(dx * dx + dy * dy) + 1.f);
                float A = *ap, Bc = *bp, C = *cp, D = *dp;
                float sig = 1.f / (1.f + expf(-(A * tsn + Bc)));
                out[bb * K + tid] = (C - sig) * (dist_sim - D);
            }
            if (tid == 0) {
                g_qflag[bb] = 0;
                __threadfence();
                atomicExch(&g_bcnt[bb], 0);
            }
        }
    }
}

// ---------------------------------------------------------------------------
extern "C" void kernel_launch(void* const* d_in, const int* in_sizes, int n_in,
                              void* d_out, int out_size) {
    const int*   qbf  = (const int*)d_in[0];
    const int*   pbf  = (const int*)d_in[1];
    const float* qloc = (const float*)d_in[2];
    const float* ploc = (const float*)d_in[3];
    const float* cw   = (const float*)d_in[4];
    const float* qW1  = (const float*)d_in[5];
    const float* qb1  = (const float*)d_in[6];
    const float* qW2  = (const float*)d_in[7];
    const float* qb2  = (const float*)d_in[8];
    const float* pW1  = (const float*)d_in[9];
    const float* pb1  = (const float*)d_in[10];
    const float* pW2  = (const float*)d_in[11];
    const float* pb2  = (const float*)d_in[12];
    const float* qew  = (const float*)d_in[13];
    const float* pew  = (const float*)d_in[14];
    const float* qa0  = (const float*)d_in[15];
    const float* qa1  = (const float*)d_in[16];
    const float* qa2  = (const float*)d_in[17];
    const float* pa0  = (const float*)d_in[18];
    const float* pa1  = (const float*)d_in[19];
    const float* pa2  = (const float*)d_in[20];
    const float* inda = (const float*)d_in[21];
    const float* a    = (const float*)d_in[22];
    const float* b    = (const float*)d_in[23];
    const float* c    = (const float*)d_in[24];
    const float* d    = (const float*)d_in[25];
    float* out = (float*)d_out;

    urban_kernel<<<NBLK, NT>>>(qbf, pbf, qloc, ploc, cw,
                               qW1, qb1, qW2, qb2,
                               pW1, pb1, pW2, pb2,
                               qew, pew,
                               qa0, qa1, qa2, pa0, pa1, pa2,
                               inda, a, b, c, d, out);
}

// round 13
// speedup vs baseline: 1.0841x; 1.0654x over previous
#include <cuda_runtime.h>
#include <cuda_bf16.h>
#include <cuda_fp16.h>
#include <math.h>

#define PAD 8192
#define B 32
#define K 32
#define L 128
#define H1 512
#define H2 64
#define BAGS 4
#define NT 512
#define XS 516          // float stride per poi bag (2064B, 16B multiple)
#define HS 68           // multiple of 4 -> float4-safe
#define NQBLK 32
#define NPBLK 256
#define NBLK (NQBLK + NPBLK)

__device__ __align__(16) __half g_cwh[(PAD + 1) * H1];   // fp16 codebook mirror
__device__ float g_qsw[B * L];
__device__ float g_ts[B * K];
__device__ int   g_qflag[B];
__device__ int   g_bcnt[B];

__device__ __forceinline__ float prelu(float x, float a) {
    return x >= 0.f ? x : a * x;
}

// ---------------------------------------------------------------------------
// Kernel 1: fp32 codebook -> fp16 mirror (deterministic, rewritten per launch)
// ---------------------------------------------------------------------------
struct __align__(8) h2x2 { __half2 a, b; };

__global__ __launch_bounds__(512)
void convert_kernel(const float* __restrict__ cw) {
    const size_t n4 = (size_t)(PAD + 1) * H1 / 4;
    const float4* src = (const float4*)cw;
    h2x2* dst = (h2x2*)g_cwh;
    for (size_t t = (size_t)blockIdx.x * blockDim.x + threadIdx.x; t < n4;
         t += (size_t)gridDim.x * blockDim.x) {
        float4 v = __ldg(src + t);
        h2x2 o;
        o.a = __floats2half2_rn(v.x, v.y);
        o.b = __floats2half2_rn(v.z, v.w);
        dst[t] = o;
    }
}

// ---------------------------------------------------------------------------
// Kernel 2: fused query + poi + epilogue
// ---------------------------------------------------------------------------
__global__ __launch_bounds__(NT, 2)
void urban_kernel(const int* __restrict__ qbf,
                  const int* __restrict__ pbf,
                  const float* __restrict__ qloc,
                  const float* __restrict__ ploc,
                  const float* __restrict__ cw,
                  const float* __restrict__ qW1, const float* __restrict__ qb1,
                  const float* __restrict__ qW2, const float* __restrict__ qb2,
                  const float* __restrict__ pW1, const float* __restrict__ pb1,
                  const float* __restrict__ pW2, const float* __restrict__ pb2,
                  const float* __restrict__ qew, const float* __restrict__ pew,
                  const float* __restrict__ qa0p, const float* __restrict__ qa1p,
                  const float* __restrict__ qa2p, const float* __restrict__ pa0p,
                  const float* __restrict__ pa1p, const float* __restrict__ pa2p,
                  const float* __restrict__ indap,
                  const float* __restrict__ ap, const float* __restrict__ bp,
                  const float* __restrict__ cp, const float* __restrict__ dp,
                  float* __restrict__ out) {
    __shared__ __align__(16) int qidx[L];
    __shared__ __align__(16) int pidx[BAGS * L];
    __shared__ unsigned bitmap[BAGS * 256];
    __shared__ int      s_wcnt[16];
    __shared__ __align__(16) float x[BAGS * XS];
    __shared__ __align__(16) float qx[H1];
    __shared__ float    mp[8 * 256];
    __shared__ float    qpart[8 * 64];
    __shared__ __align__(16) float h1s[BAGS * HS];
    __shared__ __align__(16) float phs[BAGS * HS];
    __shared__ float    qh1[H2];
    __shared__ __align__(16) float qh[H2];
    __shared__ float    wpart[16];
    __shared__ int      s_is_last;

    const int tid = threadIdx.x;
    const int bid = blockIdx.x;

    if (bid < NQBLK) {
        // ================= QUERY BLOCK: one b (fp32 codebook) =================
        const int b = bid;
        const float a0 = *qa0p, a1 = *qa1p, a2 = *qa2p;
        const float ind_a = *indap;

        if (tid < L) {
            int v = qbf[(size_t)b * L + tid];
            qidx[tid] = v;
            unsigned bal = __ballot_sync(0xffffffffu, v != PAD);
            if ((tid & 31) == 0) s_wcnt[tid >> 5] = __popc(bal);
        }
        __syncthreads();

        {
            const int c = tid;
            const int cnt = s_wcnt[0] + s_wcnt[1] + s_wcnt[2] + s_wcnt[3];
            float accA = 0.f, accB = 0.f;
            if (cnt == L) {
#pragma unroll 4
                for (int l4 = 0; l4 < 32; l4++) {
                    int4 v = ((const int4*)qidx)[l4];
                    float r0 = __ldg(cw + (size_t)v.x * H1 + c);
                    float r1 = __ldg(cw + (size_t)v.y * H1 + c);
                    float r2 = __ldg(cw + (size_t)v.z * H1 + c);
                    float r3 = __ldg(cw + (size_t)v.w * H1 + c);
                    accA += r0 + r1;
                    accB += r2 + r3;
                }
                qx[c] = prelu((accA + accB) * (1.f / (float)L), a0);
            } else {
#pragma unroll 4
                for (int l = 0; l < L; l++) {
                    int v = qidx[l];
                    float m = (v != PAD) ? 1.f : 0.f;
                    accA = fmaf(m, __ldg(cw + (size_t)v * H1 + c), accA);
                }
                float inv = cnt > 0 ? 1.f / (float)cnt : 0.f;
                qx[c] = prelu(accA * inv, a0);
            }
        }
        __syncthreads();

        {
            int j = tid & 63, dpp = tid >> 6;
            const float* w = qW1 + (size_t)(dpp * 64) * H2 + j;
            const float4* xq4 = (const float4*)(&qx[dpp * 64]);
            float acc = 0.f;
#pragma unroll 4
            for (int d4 = 0; d4 < 16; d4++) {
                float4 xv = xq4[d4];
                acc = fmaf(xv.x, __ldg(w + (d4 * 4 + 0) * H2), acc);
                acc = fmaf(xv.y, __ldg(w + (d4 * 4 + 1) * H2), acc);
                acc = fmaf(xv.z, __ldg(w + (d4 * 4 + 2) * H2), acc);
                acc = fmaf(xv.w, __ldg(w + (d4 * 4 + 3) * H2), acc);
            }
            qpart[dpp * 64 + j] = acc;
        }
        __syncthreads();
        if (tid < H2) {
            float acc = qb1[tid];
#pragma unroll
            for (int p = 0; p < 8; p++) acc += qpart[p * 64 + tid];
            qh1[tid] = prelu(acc, a1);
        }
        __syncthreads();
        if (tid < 256) {
            int j = tid & 63, dpp = tid >> 6;
            const float* w = qW2 + (size_t)(dpp * 16) * H2 + j;
            float acc = 0.f;
#pragma unroll
            for (int d = 0; d < 16; d++)
                acc = fmaf(qh1[dpp * 16 + d], __ldg(w + d * H2), acc);
            qpart[dpp * 64 + j] = acc;
        }
        __syncthreads();
        if (tid < H2) {
            float acc = qb2[tid] + qpart[tid] + qpart[64 + tid] +
                        qpart[128 + tid] + qpart[192 + tid];
            qh[tid] = prelu(acc, a2);
        }
        __syncthreads();

        if (tid < L) {
            int v = qidx[tid];
            float s = 0.f;
            if (v != PAD) {
                const float4* qr4 = (const float4*)(qew + (size_t)v * H2);
                const float4* qh4 = (const float4*)qh;
                float qd = 0.f;
#pragma unroll
                for (int h = 0; h < 16; h++) {
                    float4 r = __ldg(qr4 + h), q = qh4[h];
                    qd += r.x * q.x + r.y * q.y + r.z * q.z + r.w * q.w;
                }
                s = prelu(qd, ind_a) + 1.f;
            }
            __stcg(&g_qsw[b * L + tid], s);
        }
        __syncthreads();
        if (tid == 0) {
            __threadfence();
            atomicExch(&g_qflag[b], 1);
        }
    } else {
        // ================= POI BLOCK: 4 (b,k) pairs, fp16 gather =================
        const int pair0 = (bid - NQBLK) * BAGS;
        const int bb = pair0 >> 5;
        const float a0 = *pa0p, a1 = *pa1p, a2 = *pa2p;
        const float ind_a = *indap;

        {
            int v = pbf[(size_t)pair0 * L + tid];
            pidx[tid] = v;
            unsigned bal = __ballot_sync(0xffffffffu, v != PAD);
            if ((tid & 31) == 0) s_wcnt[tid >> 5] = __popc(bal);
        }
        if (tid < L) qidx[tid] = qbf[(size_t)bb * L + tid];
        {
            bitmap[tid] = 0u;
            bitmap[tid + 512] = 0u;
        }
        __syncthreads();

        // ---- gather: 4 bags x 128 slots of 4 dims; fp16 table (8B/row/thread)
        {
            const int g = tid >> 7, slot = tid & 127;
            const int* ip = &pidx[g * L];
            const uint2* cwh2 = (const uint2*)g_cwh;   // 8B units; row = 128 units
            float4 aA = make_float4(0.f, 0.f, 0.f, 0.f);
            float4 aB = make_float4(0.f, 0.f, 0.f, 0.f);
            const int cnt = s_wcnt[g * 4] + s_wcnt[g * 4 + 1] +
                            s_wcnt[g * 4 + 2] + s_wcnt[g * 4 + 3];
            if (cnt == L) {
#pragma unroll 4
                for (int l4 = 0; l4 < 32; l4++) {
                    int4 v = ((const int4*)ip)[l4];
                    uint2 u0 = __ldg(cwh2 + (size_t)v.x * 128 + slot);
                    uint2 u1 = __ldg(cwh2 + (size_t)v.y * 128 + slot);
                    uint2 u2 = __ldg(cwh2 + (size_t)v.z * 128 + slot);
                    uint2 u3 = __ldg(cwh2 + (size_t)v.w * 128 + slot);
                    float2 p0 = __half22float2(*(const __half2*)&u0.x);
                    float2 p1 = __half22float2(*(const __half2*)&u0.y);
                    float2 p2 = __half22float2(*(const __half2*)&u1.x);
                    float2 p3 = __half22float2(*(const __half2*)&u1.y);
                    aA.x += p0.x + p2.x; aA.y += p0.y + p2.y;
                    aA.z += p1.x + p3.x; aA.w += p1.y + p3.y;
                    float2 p4 = __half22float2(*(const __half2*)&u2.x);
                    float2 p5 = __half22float2(*(const __half2*)&u2.y);
                    float2 p6 = __half22float2(*(const __half2*)&u3.x);
                    float2 p7 = __half22float2(*(const __half2*)&u3.y);
                    aB.x += p4.x + p6.x; aB.y += p4.y + p6.y;
                    aB.z += p5.x + p7.x; aB.w += p5.y + p7.y;
                }
                const float inv = 1.f / (float)L;
                float4 o;
                o.x = prelu((aA.x + aB.x) * inv, a0);
                o.y = prelu((aA.y + aB.y) * inv, a0);
                o.z = prelu((aA.z + aB.z) * inv, a0);
                o.w = prelu((aA.w + aB.w) * inv, a0);
                *(float4*)(&x[g * XS] + slot * 4) = o;
            } else {
#pragma unroll 4
                for (int l = 0; l < L; l++) {
                    int v = ip[l];
                    float m = (v != PAD) ? 1.f : 0.f;
                    uint2 u = __ldg(cwh2 + (size_t)v * 128 + slot);
                    float2 p0 = __half22float2(*(const __half2*)&u.x);
                    float2 p1 = __half22float2(*(const __half2*)&u.y);
                    aA.x = fmaf(m, p0.x, aA.x); aA.y = fmaf(m, p0.y, aA.y);
                    aA.z = fmaf(m, p1.x, aA.z); aA.w = fmaf(m, p1.y, aA.w);
                }
                float inv = cnt > 0 ? 1.f / (float)cnt : 0.f;
                float4 o;
                o.x = prelu(aA.x * inv, a0); o.y = prelu(aA.y * inv, a0);
                o.z = prelu(aA.z * inv, a0); o.w = prelu(aA.w * inv, a0);
                *(float4*)(&x[g * XS] + slot * 4) = o;
            }
        }
        __syncthreads();

        // ---- bitmap build (same phase as MLP1) ----
        {
            int v = pidx[tid];
            if (v != PAD)
                atomicOr(&bitmap[(tid >> 7) * 256 + (v >> 5)], 1u << (v & 31));
        }
        // ---- MLP1: one W1 load feeds 4 bag-accumulators; float4 LDS ----
        {
            int j = tid & 63, dpp = tid >> 6;   // 8 d-parts of 64
            const float* w = pW1 + (size_t)(dpp * 64) * H2 + j;
            const float4* x0 = (const float4*)(&x[0 * XS + dpp * 64]);
            const float4* x1 = (const float4*)(&x[1 * XS + dpp * 64]);
            const float4* x2 = (const float4*)(&x[2 * XS + dpp * 64]);
            const float4* x3 = (const float4*)(&x[3 * XS + dpp * 64]);
            float f0 = 0.f, f1 = 0.f, f2 = 0.f, f3 = 0.f;
#pragma unroll 4
            for (int d4 = 0; d4 < 16; d4++) {
                float4 a = x0[d4], bv = x1[d4], cv = x2[d4], dv = x3[d4];
#pragma unroll
                for (int u = 0; u < 4; u++) {
                    float wv = __ldg(w + (d4 * 4 + u) * H2);
                    f0 = fmaf((&a.x)[u], wv, f0);
                    f1 = fmaf((&bv.x)[u], wv, f1);
                    f2 = fmaf((&cv.x)[u], wv, f2);
                    f3 = fmaf((&dv.x)[u], wv, f3);
                }
            }
            mp[dpp * 256 + j]       = f0;
            mp[dpp * 256 + 64 + j]  = f1;
            mp[dpp * 256 + 128 + j] = f2;
            mp[dpp * 256 + 192 + j] = f3;
        }
        __syncthreads();
        if (tid < 256) {
            int j = tid & 63, g = tid >> 6;
            float acc = pb1[j];
#pragma unroll
            for (int p = 0; p < 8; p++) acc += mp[p * 256 + g * 64 + j];
            h1s[g * HS + j] = prelu(acc, a1);
        }
        __syncthreads();
        // ---- MLP2: one W2 load feeds 4 bags; float4 LDS ----
        if (tid < 256) {
            int j = tid & 63, dpp = tid >> 6;   // 4 d-parts of 16
            const float* w = pW2 + (size_t)(dpp * 16) * H2 + j;
            const float4* h0 = (const float4*)(&h1s[0 * HS + dpp * 16]);
            const float4* h1 = (const float4*)(&h1s[1 * HS + dpp * 16]);
            const float4* h2 = (const float4*)(&h1s[2 * HS + dpp * 16]);
            const float4* h3 = (const float4*)(&h1s[3 * HS + dpp * 16]);
            float f0 = 0.f, f1 = 0.f, f2 = 0.f, f3 = 0.f;
#pragma unroll
            for (int d4 = 0; d4 < 4; d4++) {
                float4 a = h0[d4], bv = h1[d4], cv = h2[d4], dv = h3[d4];
#pragma unroll
                for (int u = 0; u < 4; u++) {
                    float wv = __ldg(w + (d4 * 4 + u) * H2);
                    f0 = fmaf((&a.x)[u], wv, f0);
                    f1 = fmaf((&bv.x)[u], wv, f1);
                    f2 = fmaf((&cv.x)[u], wv, f2);
                    f3 = fmaf((&dv.x)[u], wv, f3);
                }
            }
            mp[dpp * 256 + j]       = f0;
            mp[dpp * 256 + 64 + j]  = f1;
            mp[dpp * 256 + 128 + j] = f2;
            mp[dpp * 256 + 192 + j] = f3;
        }
        __syncthreads();
        if (tid < 256) {
            int j = tid & 63, g = tid >> 6;
            float acc = pb2[j] + mp[g * 64 + j] + mp[256 + g * 64 + j] +
                        mp[512 + g * 64 + j] + mp[768 + g * 64 + j];
            phs[g * HS + j] = prelu(acc, a2);
        }
        if (tid == 0) {
            while (((volatile int*)g_qflag)[bb] == 0) {}
            __threadfence();
        }
        __syncthreads();

        // ---- probe + p-side dot; qsw read direct from L2 ----
        {
            int g = tid >> 7, i = tid & 127;
            int v = qidx[i];
            float val = 0.f;
            bool hit = (v != PAD) &&
                       ((bitmap[g * 256 + (v >> 5)] >> (v & 31)) & 1u);
            float qs = __ldcg(&g_qsw[bb * L + i]);
            if (hit) {
                const float4* pr4 = (const float4*)(pew + (size_t)v * H2);
                const float4* ph4 = (const float4*)(&phs[g * HS]);
                float pd = 0.f;
#pragma unroll
                for (int h = 0; h < 16; h++) {
                    float4 r = __ldg(pr4 + h), p = ph4[h];
                    pd += r.x * p.x + r.y * p.y + r.z * p.z + r.w * p.w;
                }
                val = qs * (prelu(pd, ind_a) + 1.f);
            }
#pragma unroll
            for (int off = 16; off > 0; off >>= 1)
                val += __shfl_xor_sync(0xffffffffu, val, off);
            if ((tid & 31) == 0) wpart[tid >> 5] = val;
        }
        __syncthreads();
        if (tid < BAGS) {
            float s = wpart[tid * 4] + wpart[tid * 4 + 1] +
                      wpart[tid * 4 + 2] + wpart[tid * 4 + 3];
            __stcg(&g_ts[pair0 + tid], s);
        }

        // ---- per-b distributed epilogue ----
        if (tid == 0) {
            __threadfence();
            s_is_last = (atomicAdd(&g_bcnt[bb], 1) == 7);
        }
        __syncthreads();
        if (s_is_last) {
            if (tid < K) {
                float ts = __ldcg(&g_ts[bb * K + tid]);
                float m = ts;
#pragma unroll
                for (int off = 16; off > 0; off >>= 1)
                    m = fmaxf(m, __shfl_xor_sync(0xffffffffu, m, off));
                float tsn = (2.f * ts - m) / (m + 1e-6f);
                float2 pl = __ldg((const float2*)(ploc + (size_t)(bb * K + tid) * 2));
                float dx = qloc[bb * 2]     - pl.x;
                float dy = qloc[bb * 2 + 1] - pl.y;
                float dist_sim = -logf(sqrtf(dx * dx + dy * dy) + 1.f);
                float A = *ap, Bc = *bp, C = *cp, D = *dp;
                float sig = 1.f / (1.f + expf(-(A * tsn + Bc)));
                out[bb * K + tid] = (C - sig) * (dist_sim - D);
            }
            if (tid == 0) {
                g_qflag[bb] = 0;
                __threadfence();
                atomicExch(&g_bcnt[bb], 0);
            }
        }
    }
}

// ---------------------------------------------------------------------------
extern "C" void kernel_launch(void* const* d_in, const int* in_sizes, int n_in,
                              void* d_out, int out_size) {
    const int*   qbf  = (const int*)d_in[0];
    const int*   pbf  = (const int*)d_in[1];
    const float* qloc = (const float*)d_in[2];
    const float* ploc = (const float*)d_in[3];
    const float* cw   = (const float*)d_in[4];
    const float* qW1  = (const float*)d_in[5];
    const float* qb1  = (const float*)d_in[6];
    const float* qW2  = (const float*)d_in[7];
    const float* qb2  = (const float*)d_in[8];
    const float* pW1  = (const float*)d_in[9];
    const float* pb1  = (const float*)d_in[10];
    const float* pW2  = (const float*)d_in[11];
    const float* pb2  = (const float*)d_in[12];
    const float* qew  = (const float*)d_in[13];
    const float* pew  = (const float*)d_in[14];
    const float* qa0  = (const float*)d_in[15];
    const float* qa1  = (const float*)d_in[16];
    const float* qa2  = (const float*)d_in[17];
    const float* pa0  = (const float*)d_in[18];
    const float* pa1  = (const float*)d_in[19];
    const float* pa2  = (const float*)d_in[20];
    const float* inda = (const float*)d_in[21];
    const float* a    = (const float*)d_in[22];
    const float* b    = (const float*)d_in[23];
    const float* c    = (const float*)d_in[24];
    const float* d    = (const float*)d_in[25];
    float* out = (float*)d_out;

    convert_kernel<<<256, 512>>>(cw);
    urban_kernel<<<NBLK, NT>>>(qbf, pbf, qloc, ploc, cw,
                               qW1, qb1, qW2, qb2,
                               pW1, pb1, pW2, pb2,
                               qew, pew,
                               qa0, qa1, qa2, pa0, pa1, pa2,
                               inda, a, b, c, d, out);
}

// round 14
// speedup vs baseline: 1.1732x; 1.0822x over previous
#include <cuda_runtime.h>
#include <cuda_bf16.h>
#include <cuda_fp16.h>
#include <math.h>

#define PAD 8192
#define B 32
#define K 32
#define L 128
#define H1 512
#define H2 64
#define BAGS 4
#define NT 512
#define XS 516          // float stride per poi bag (2064B, 16B multiple)
#define HS 68           // multiple of 4 -> float4-safe
#define NQBLK 32
#define NPBLK 256
#define NBLK (NQBLK + NPBLK)

__device__ __align__(16) __half g_cwh[(PAD + 1) * H1];   // fp16 codebook mirror
__device__ float g_qsw[B * L];
__device__ float g_ts[B * K];
__device__ int   g_qflag[B];
__device__ int   g_bcnt[B];

__device__ __forceinline__ float prelu(float x, float a) {
    return x >= 0.f ? x : a * x;
}

// ---------------------------------------------------------------------------
// Kernel 1: fp32 codebook -> fp16 mirror
// ---------------------------------------------------------------------------
struct __align__(8) h2x2 { __half2 a, b; };

__global__ __launch_bounds__(512)
void convert_kernel(const float* __restrict__ cw) {
    const size_t n4 = (size_t)(PAD + 1) * H1 / 4;
    const float4* src = (const float4*)cw;
    h2x2* dst = (h2x2*)g_cwh;
    for (size_t t = (size_t)blockIdx.x * blockDim.x + threadIdx.x; t < n4;
         t += (size_t)gridDim.x * blockDim.x) {
        float4 v = __ldg(src + t);
        h2x2 o;
        o.a = __floats2half2_rn(v.x, v.y);
        o.b = __floats2half2_rn(v.z, v.w);
        dst[t] = o;
    }
}

// ---------------------------------------------------------------------------
// Kernel 2: fused query + poi + epilogue
// ---------------------------------------------------------------------------
__global__ __launch_bounds__(NT, 2)
void urban_kernel(const int* __restrict__ qbf,
                  const int* __restrict__ pbf,
                  const float* __restrict__ qloc,
                  const float* __restrict__ ploc,
                  const float* __restrict__ cw,
                  const float* __restrict__ qW1, const float* __restrict__ qb1,
                  const float* __restrict__ qW2, const float* __restrict__ qb2,
                  const float* __restrict__ pW1, const float* __restrict__ pb1,
                  const float* __restrict__ pW2, const float* __restrict__ pb2,
                  const float* __restrict__ qew, const float* __restrict__ pew,
                  const float* __restrict__ qa0p, const float* __restrict__ qa1p,
                  const float* __restrict__ qa2p, const float* __restrict__ pa0p,
                  const float* __restrict__ pa1p, const float* __restrict__ pa2p,
                  const float* __restrict__ indap,
                  const float* __restrict__ ap, const float* __restrict__ bp,
                  const float* __restrict__ cp, const float* __restrict__ dp,
                  float* __restrict__ out) {
    __shared__ __align__(16) int qidx[L];
    __shared__ __align__(16) int pidx[BAGS * L];
    __shared__ unsigned bitmap[BAGS * 256];
    __shared__ int      s_wcnt[16];
    __shared__ __align__(16) float x[BAGS * XS];
    __shared__ __align__(16) float qx[H1];
    __shared__ __align__(16) float mp[8 * 256];     // MLP partials / gather scratch
    __shared__ float    qpart[8 * 64];
    __shared__ __align__(16) float h1s[BAGS * HS];
    __shared__ __align__(16) float phs[BAGS * HS];
    __shared__ float    qh1[H2];
    __shared__ __align__(16) float qh[H2];
    __shared__ float    wpart[16];
    __shared__ int      s_is_last;

    const int tid = threadIdx.x;
    const int bid = blockIdx.x;

    if (bid < NQBLK) {
        // ================= QUERY BLOCK: one b (fp32 codebook) =================
        const int b = bid;
        const float a0 = *qa0p, a1 = *qa1p, a2 = *qa2p;
        const float ind_a = *indap;

        if (tid < L) {
            int v = qbf[(size_t)b * L + tid];
            qidx[tid] = v;
            unsigned bal = __ballot_sync(0xffffffffu, v != PAD);
            if ((tid & 31) == 0) s_wcnt[tid >> 5] = __popc(bal);
        }
        __syncthreads();

        {
            const int c = tid;
            const int cnt = s_wcnt[0] + s_wcnt[1] + s_wcnt[2] + s_wcnt[3];
            float accA = 0.f, accB = 0.f;
            if (cnt == L) {
#pragma unroll 4
                for (int l4 = 0; l4 < 32; l4++) {
                    int4 v = ((const int4*)qidx)[l4];
                    float r0 = __ldg(cw + (size_t)v.x * H1 + c);
                    float r1 = __ldg(cw + (size_t)v.y * H1 + c);
                    float r2 = __ldg(cw + (size_t)v.z * H1 + c);
                    float r3 = __ldg(cw + (size_t)v.w * H1 + c);
                    accA += r0 + r1;
                    accB += r2 + r3;
                }
                qx[c] = prelu((accA + accB) * (1.f / (float)L), a0);
            } else {
#pragma unroll 4
                for (int l = 0; l < L; l++) {
                    int v = qidx[l];
                    float m = (v != PAD) ? 1.f : 0.f;
                    accA = fmaf(m, __ldg(cw + (size_t)v * H1 + c), accA);
                }
                float inv = cnt > 0 ? 1.f / (float)cnt : 0.f;
                qx[c] = prelu(accA * inv, a0);
            }
        }
        __syncthreads();

        {
            int j = tid & 63, dpp = tid >> 6;
            const float* w = qW1 + (size_t)(dpp * 64) * H2 + j;
            const float4* xq4 = (const float4*)(&qx[dpp * 64]);
            float acc = 0.f;
#pragma unroll 4
            for (int d4 = 0; d4 < 16; d4++) {
                float4 xv = xq4[d4];
                acc = fmaf(xv.x, __ldg(w + (d4 * 4 + 0) * H2), acc);
                acc = fmaf(xv.y, __ldg(w + (d4 * 4 + 1) * H2), acc);
                acc = fmaf(xv.z, __ldg(w + (d4 * 4 + 2) * H2), acc);
                acc = fmaf(xv.w, __ldg(w + (d4 * 4 + 3) * H2), acc);
            }
            qpart[dpp * 64 + j] = acc;
        }
        __syncthreads();
        if (tid < H2) {
            float acc = qb1[tid];
#pragma unroll
            for (int p = 0; p < 8; p++) acc += qpart[p * 64 + tid];
            qh1[tid] = prelu(acc, a1);
        }
        __syncthreads();
        if (tid < 256) {
            int j = tid & 63, dpp = tid >> 6;
            const float* w = qW2 + (size_t)(dpp * 16) * H2 + j;
            float acc = 0.f;
#pragma unroll
            for (int d = 0; d < 16; d++)
                acc = fmaf(qh1[dpp * 16 + d], __ldg(w + d * H2), acc);
            qpart[dpp * 64 + j] = acc;
        }
        __syncthreads();
        if (tid < H2) {
            float acc = qb2[tid] + qpart[tid] + qpart[64 + tid] +
                        qpart[128 + tid] + qpart[192 + tid];
            qh[tid] = prelu(acc, a2);
        }
        __syncthreads();

        if (tid < L) {
            int v = qidx[tid];
            float s = 0.f;
            if (v != PAD) {
                const float4* qr4 = (const float4*)(qew + (size_t)v * H2);
                const float4* qh4 = (const float4*)qh;
                float qd = 0.f;
#pragma unroll
                for (int h = 0; h < 16; h++) {
                    float4 r = __ldg(qr4 + h), q = qh4[h];
                    qd += r.x * q.x + r.y * q.y + r.z * q.z + r.w * q.w;
                }
                s = prelu(qd, ind_a) + 1.f;
            }
            __stcg(&g_qsw[b * L + tid], s);
        }
        __syncthreads();
        if (tid == 0) {
            __threadfence();
            atomicExch(&g_qflag[b], 1);
        }
    } else {
        // ================= POI BLOCK: 4 (b,k) pairs, fp16 gather =================
        const int pair0 = (bid - NQBLK) * BAGS;
        const int bb = pair0 >> 5;
        const float a0 = *pa0p, a1 = *pa1p, a2 = *pa2p;
        const float ind_a = *indap;

        {
            int v = pbf[(size_t)pair0 * L + tid];
            pidx[tid] = v;
            unsigned bal = __ballot_sync(0xffffffffu, v != PAD);
            if ((tid & 31) == 0) s_wcnt[tid >> 5] = __popc(bal);
        }
        if (tid < L) qidx[tid] = qbf[(size_t)bb * L + tid];
        {
            bitmap[tid] = 0u;
            bitmap[tid + 512] = 0u;
        }
        __syncthreads();

        // ---- gather: thread = (bag, 16B-chunk, row-half); LDG.128 + HADD2 ----
        const int g = tid >> 7;
        const int chunk = tid & 63;       // 8 halfs per chunk
        const int rh = (tid >> 6) & 1;    // row half
        {
            const int* ip = &pidx[g * L] + rh * 64;
            const uint4* cwh4 = (const uint4*)g_cwh;   // row = 64 uint4
            const int cnt = s_wcnt[g * 4] + s_wcnt[g * 4 + 1] +
                            s_wcnt[g * 4 + 2] + s_wcnt[g * 4 + 3];
            float acc[8];
#pragma unroll
            for (int i = 0; i < 8; i++) acc[i] = 0.f;
            if (cnt == L) {
#pragma unroll 4
                for (int p = 0; p < 32; p++) {
                    int2 v = ((const int2*)ip)[p];
                    uint4 u0 = __ldg(cwh4 + (size_t)v.x * 64 + chunk);
                    uint4 u1 = __ldg(cwh4 + (size_t)v.y * 64 + chunk);
                    __half2 h0 = __hadd2(*(const __half2*)&u0.x, *(const __half2*)&u1.x);
                    __half2 h1 = __hadd2(*(const __half2*)&u0.y, *(const __half2*)&u1.y);
                    __half2 h2 = __hadd2(*(const __half2*)&u0.z, *(const __half2*)&u1.z);
                    __half2 h3 = __hadd2(*(const __half2*)&u0.w, *(const __half2*)&u1.w);
                    float2 f0 = __half22float2(h0);
                    float2 f1 = __half22float2(h1);
                    float2 f2 = __half22float2(h2);
                    float2 f3 = __half22float2(h3);
                    acc[0] += f0.x; acc[1] += f0.y;
                    acc[2] += f1.x; acc[3] += f1.y;
                    acc[4] += f2.x; acc[5] += f2.y;
                    acc[6] += f3.x; acc[7] += f3.y;
                }
            } else {
                for (int l = 0; l < 64; l++) {
                    int v = ip[l];
                    float m = (v != PAD) ? 1.f : 0.f;
                    uint4 u = __ldg(cwh4 + (size_t)v * 64 + chunk);
                    float2 f0 = __half22float2(*(const __half2*)&u.x);
                    float2 f1 = __half22float2(*(const __half2*)&u.y);
                    float2 f2 = __half22float2(*(const __half2*)&u.z);
                    float2 f3 = __half22float2(*(const __half2*)&u.w);
                    acc[0] = fmaf(m, f0.x, acc[0]); acc[1] = fmaf(m, f0.y, acc[1]);
                    acc[2] = fmaf(m, f1.x, acc[2]); acc[3] = fmaf(m, f1.y, acc[3]);
                    acc[4] = fmaf(m, f2.x, acc[4]); acc[5] = fmaf(m, f2.y, acc[5]);
                    acc[6] = fmaf(m, f3.x, acc[6]); acc[7] = fmaf(m, f3.y, acc[7]);
                }
            }
            // row-half 1 publishes partials through mp scratch
            if (rh) {
                float* s = &mp[(g * 64 + chunk) * 8];
                *(float4*)s       = make_float4(acc[0], acc[1], acc[2], acc[3]);
                *(float4*)(s + 4) = make_float4(acc[4], acc[5], acc[6], acc[7]);
            }
            __syncthreads();
            if (!rh) {
                const float* s = &mp[(g * 64 + chunk) * 8];
                float inv = cnt > 0 ? 1.f / (float)cnt : 0.f;
                float4 o0, o1;
                o0.x = prelu((acc[0] + s[0]) * inv, a0);
                o0.y = prelu((acc[1] + s[1]) * inv, a0);
                o0.z = prelu((acc[2] + s[2]) * inv, a0);
                o0.w = prelu((acc[3] + s[3]) * inv, a0);
                o1.x = prelu((acc[4] + s[4]) * inv, a0);
                o1.y = prelu((acc[5] + s[5]) * inv, a0);
                o1.z = prelu((acc[6] + s[6]) * inv, a0);
                o1.w = prelu((acc[7] + s[7]) * inv, a0);
                *(float4*)(&x[g * XS + chunk * 8])     = o0;
                *(float4*)(&x[g * XS + chunk * 8 + 4]) = o1;
            }
        }
        __syncthreads();

        // ---- bitmap build (same phase as MLP1) ----
        {
            int v = pidx[tid];
            if (v != PAD)
                atomicOr(&bitmap[(tid >> 7) * 256 + (v >> 5)], 1u << (v & 31));
        }
        // ---- MLP1: one W1 load feeds 4 bag-accumulators; float4 LDS ----
        {
            int j = tid & 63, dpp = tid >> 6;   // 8 d-parts of 64
            const float* w = pW1 + (size_t)(dpp * 64) * H2 + j;
            const float4* x0 = (const float4*)(&x[0 * XS + dpp * 64]);
            const float4* x1 = (const float4*)(&x[1 * XS + dpp * 64]);
            const float4* x2 = (const float4*)(&x[2 * XS + dpp * 64]);
            const float4* x3 = (const float4*)(&x[3 * XS + dpp * 64]);
            float f0 = 0.f, f1 = 0.f, f2 = 0.f, f3 = 0.f;
#pragma unroll 4
            for (int d4 = 0; d4 < 16; d4++) {
                float4 a = x0[d4], bv = x1[d4], cv = x2[d4], dv = x3[d4];
#pragma unroll
                for (int u = 0; u < 4; u++) {
                    float wv = __ldg(w + (d4 * 4 + u) * H2);
                    f0 = fmaf((&a.x)[u], wv, f0);
                    f1 = fmaf((&bv.x)[u], wv, f1);
                    f2 = fmaf((&cv.x)[u], wv, f2);
                    f3 = fmaf((&dv.x)[u], wv, f3);
                }
            }
            __syncthreads();   // mp scratch reuse: gather partials consumed above
            mp[dpp * 256 + j]       = f0;
            mp[dpp * 256 + 64 + j]  = f1;
            mp[dpp * 256 + 128 + j] = f2;
            mp[dpp * 256 + 192 + j] = f3;
        }
        __syncthreads();
        if (tid < 256) {
            int j = tid & 63, g2 = tid >> 6;
            float acc = pb1[j];
#pragma unroll
            for (int p = 0; p < 8; p++) acc += mp[p * 256 + g2 * 64 + j];
            h1s[g2 * HS + j] = prelu(acc, a1);
        }
        __syncthreads();
        // ---- MLP2: one W2 load feeds 4 bags; float4 LDS ----
        if (tid < 256) {
            int j = tid & 63, dpp = tid >> 6;   // 4 d-parts of 16
            const float* w = pW2 + (size_t)(dpp * 16) * H2 + j;
            const float4* h0 = (const float4*)(&h1s[0 * HS + dpp * 16]);
            const float4* h1 = (const float4*)(&h1s[1 * HS + dpp * 16]);
            const float4* h2 = (const float4*)(&h1s[2 * HS + dpp * 16]);
            const float4* h3 = (const float4*)(&h1s[3 * HS + dpp * 16]);
            float f0 = 0.f, f1 = 0.f, f2 = 0.f, f3 = 0.f;
#pragma unroll
            for (int d4 = 0; d4 < 4; d4++) {
                float4 a = h0[d4], bv = h1[d4], cv = h2[d4], dv = h3[d4];
#pragma unroll
                for (int u = 0; u < 4; u++) {
                    float wv = __ldg(w + (d4 * 4 + u) * H2);
                    f0 = fmaf((&a.x)[u], wv, f0);
                    f1 = fmaf((&bv.x)[u], wv, f1);
                    f2 = fmaf((&cv.x)[u], wv, f2);
                    f3 = fmaf((&dv.x)[u], wv, f3);
                }
            }
            mp[dpp * 256 + j]       = f0;
            mp[dpp * 256 + 64 + j]  = f1;
            mp[dpp * 256 + 128 + j] = f2;
            mp[dpp * 256 + 192 + j] = f3;
        }
        __syncthreads();
        if (tid < 256) {
            int j = tid & 63, g2 = tid >> 6;
            float acc = pb2[j] + mp[g2 * 64 + j] + mp[256 + g2 * 64 + j] +
                        mp[512 + g2 * 64 + j] + mp[768 + g2 * 64 + j];
            phs[g2 * HS + j] = prelu(acc, a2);
        }
        if (tid == 0) {
            while (((volatile int*)g_qflag)[bb] == 0) {}
            __threadfence();
        }
        __syncthreads();

        // ---- probe + p-side dot; qsw read direct from L2 ----
        {
            int gg = tid >> 7, i = tid & 127;
            int v = qidx[i];
            float val = 0.f;
            bool hit = (v != PAD) &&
                       ((bitmap[gg * 256 + (v >> 5)] >> (v & 31)) & 1u);
            float qs = __ldcg(&g_qsw[bb * L + i]);
            if (hit) {
                const float4* pr4 = (const float4*)(pew + (size_t)v * H2);
                const float4* ph4 = (const float4*)(&phs[gg * HS]);
                float pd = 0.f;
#pragma unroll
                for (int h = 0; h < 16; h++) {
                    float4 r = __ldg(pr4 + h), p = ph4[h];
                    pd += r.x * p.x + r.y * p.y + r.z * p.z + r.w * p.w;
                }
                val = qs * (prelu(pd, ind_a) + 1.f);
            }
#pragma unroll
            for (int off = 16; off > 0; off >>= 1)
                val += __shfl_xor_sync(0xffffffffu, val, off);
            if ((tid & 31) == 0) wpart[tid >> 5] = val;
        }
        __syncthreads();
        if (tid < BAGS) {
            float s = wpart[tid * 4] + wpart[tid * 4 + 1] +
                      wpart[tid * 4 + 2] + wpart[tid * 4 + 3];
            __stcg(&g_ts[pair0 + tid], s);
        }

        // ---- per-b distributed epilogue ----
        if (tid == 0) {
            __threadfence();
            s_is_last = (atomicAdd(&g_bcnt[bb], 1) == 7);
        }
        __syncthreads();
        if (s_is_last) {
            if (tid < K) {
                float ts = __ldcg(&g_ts[bb * K + tid]);
                float m = ts;
#pragma unroll
                for (int off = 16; off > 0; off >>= 1)
                    m = fmaxf(m, __shfl_xor_sync(0xffffffffu, m, off));
                float tsn = (2.f * ts - m) / (m + 1e-6f);
                float2 pl = __ldg((const float2*)(ploc + (size_t)(bb * K + tid) * 2));
                float dx = qloc[bb * 2]     - pl.x;
                float dy = qloc[bb * 2 + 1] - pl.y;
                float dist_sim = -logf(sqrtf(dx * dx + dy * dy) + 1.f);
                float A = *ap, Bc = *bp, C = *cp, D = *dp;
                float sig = 1.f / (1.f + expf(-(A * tsn + Bc)));
                out[bb * K + tid] = (C - sig) * (dist_sim - D);
            }
            if (tid == 0) {
                g_qflag[bb] = 0;
                __threadfence();
                atomicExch(&g_bcnt[bb], 0);
            }
        }
    }
}

// ---------------------------------------------------------------------------
extern "C" void kernel_launch(void* const* d_in, const int* in_sizes, int n_in,
                              void* d_out, int out_size) {
    const int*   qbf  = (const int*)d_in[0];
    const int*   pbf  = (const int*)d_in[1];
    const float* qloc = (const float*)d_in[2];
    const float* ploc = (const float*)d_in[3];
    const float* cw   = (const float*)d_in[4];
    const float* qW1  = (const float*)d_in[5];
    const float* qb1  = (const float*)d_in[6];
    const float* qW2  = (const float*)d_in[7];
    const float* qb2  = (const float*)d_in[8];
    const float* pW1  = (const float*)d_in[9];
    const float* pb1  = (const float*)d_in[10];
    const float* pW2  = (const float*)d_in[11];
    const float* pb2  = (const float*)d_in[12];
    const float* qew  = (const float*)d_in[13];
    const float* pew  = (const float*)d_in[14];
    const float* qa0  = (const float*)d_in[15];
    const float* qa1  = (const float*)d_in[16];
    const float* qa2  = (const float*)d_in[17];
    const float* pa0  = (const float*)d_in[18];
    const float* pa1  = (const float*)d_in[19];
    const float* pa2  = (const float*)d_in[20];
    const float* inda = (const float*)d_in[21];
    const float* a    = (const float*)d_in[22];
    const float* b    = (const float*)d_in[23];
    const float* c    = (const float*)d_in[24];
    const float* d    = (const float*)d_in[25];
    float* out = (float*)d_out;

    convert_kernel<<<256, 512>>>(cw);
    urban_kernel<<<NBLK, NT>>>(qbf, pbf, qloc, ploc, cw,
                               qW1, qb1, qW2, qb2,
                               pW1, pb1, pW2, pb2,
                               qew, pew,
                               qa0, qa1, qa2, pa0, pa1, pa2,
                               inda, a, b, c, d, out);
}

// round 15
// speedup vs baseline: 1.1852x; 1.0102x over previous
#include <cuda_runtime.h>
#include <cuda_bf16.h>
#include <cuda_fp16.h>
#include <math.h>

#define PAD 8192
#define B 32
#define K 32
#define L 128
#define H1 512
#define H2 64
#define BAGS 4
#define NT 512
#define XS 516          // float stride per poi bag (2064B, 16B multiple)
#define HS 68
#define NQBLK 32
#define NPBLK 256
#define NBLK (NQBLK + NPBLK)

typedef unsigned long long ull;

__device__ __align__(16) __half  g_cwh[(PAD + 1) * H1];  // fp16 codebook mirror
__device__ __align__(16) __half2 g_w1h2[(H1 / 2) * H2];  // fp16 W1, d-pair packed
__device__ float g_qsw[B * L];
__device__ float g_ts[B * K];
__device__ int   g_qflag[B];
__device__ int   g_bcnt[B];

__device__ __forceinline__ float prelu(float x, float a) {
    return x >= 0.f ? x : a * x;
}
__device__ __forceinline__ ull pack_f2(float lo, float hi) {
    ull r; asm("mov.b64 %0, {%1, %2};" : "=l"(r) : "f"(lo), "f"(hi)); return r;
}
__device__ __forceinline__ void ffma2(ull& acc, ull a, ull b) {
    asm("fma.rn.f32x2 %0, %1, %2, %0;" : "+l"(acc) : "l"(a), "l"(b));
}
__device__ __forceinline__ float2 unpack_f2(ull v) {
    float2 r; asm("mov.b64 {%0, %1}, %2;" : "=f"(r.x), "=f"(r.y) : "l"(v)); return r;
}

// ---------------------------------------------------------------------------
// Kernel 1: fp32 codebook -> fp16 mirror; pW1 -> d-pair-packed fp16 mirror
// ---------------------------------------------------------------------------
struct __align__(8) h2x2 { __half2 a, b; };

__global__ __launch_bounds__(512)
void convert_kernel(const float* __restrict__ cw, const float* __restrict__ pW1) {
    const size_t n4 = (size_t)(PAD + 1) * H1 / 4;
    const float4* src = (const float4*)cw;
    h2x2* dst = (h2x2*)g_cwh;
    size_t tid0 = (size_t)blockIdx.x * blockDim.x + threadIdx.x;
    for (size_t t = tid0; t < n4; t += (size_t)gridDim.x * blockDim.x) {
        float4 v = __ldg(src + t);
        h2x2 o;
        o.a = __floats2half2_rn(v.x, v.y);
        o.b = __floats2half2_rn(v.z, v.w);
        dst[t] = o;
    }
    // W1 pack: entry t = (d2, j) holds (W1[2*d2][j], W1[2*d2+1][j])
    for (size_t t = tid0; t < (H1 / 2) * H2; t += (size_t)gridDim.x * blockDim.x) {
        int d2 = (int)(t >> 6), j = (int)(t & 63);
        g_w1h2[t] = __floats2half2_rn(__ldg(pW1 + (size_t)(2 * d2) * H2 + j),
                                      __ldg(pW1 + (size_t)(2 * d2 + 1) * H2 + j));
    }
}

// ---------------------------------------------------------------------------
// Kernel 2: fused query + poi + epilogue
// ---------------------------------------------------------------------------
__global__ __launch_bounds__(NT, 2)
void urban_kernel(const int* __restrict__ qbf,
                  const int* __restrict__ pbf,
                  const float* __restrict__ qloc,
                  const float* __restrict__ ploc,
                  const float* __restrict__ cw,
                  const float* __restrict__ qW1, const float* __restrict__ qb1,
                  const float* __restrict__ qW2, const float* __restrict__ qb2,
                  const float* __restrict__ pW1, const float* __restrict__ pb1,
                  const float* __restrict__ pW2, const float* __restrict__ pb2,
                  const float* __restrict__ qew, const float* __restrict__ pew,
                  const float* __restrict__ qa0p, const float* __restrict__ qa1p,
                  const float* __restrict__ qa2p, const float* __restrict__ pa0p,
                  const float* __restrict__ pa1p, const float* __restrict__ pa2p,
                  const float* __restrict__ indap,
                  const float* __restrict__ ap, const float* __restrict__ bp,
                  const float* __restrict__ cp, const float* __restrict__ dp,
                  float* __restrict__ out) {
    __shared__ __align__(16) int qidx[L];
    __shared__ __align__(16) int pidx[BAGS * L];
    __shared__ unsigned bitmap[BAGS * 256];
    __shared__ int      s_wcnt[16];
    __shared__ __align__(16) float x[BAGS * XS];
    __shared__ __align__(16) float qx[H1];
    __shared__ __align__(16) float mp[8 * 256];     // MLP partials / gather scratch
    __shared__ float    qpart[8 * 64];
    __shared__ __align__(16) float h1s[BAGS * HS];
    __shared__ __align__(16) float phs[BAGS * HS];
    __shared__ float    qh1[H2];
    __shared__ __align__(16) float qh[H2];
    __shared__ float    wpart[16];
    __shared__ int      s_is_last;

    const int tid = threadIdx.x;
    const int bid = blockIdx.x;

    if (bid < NQBLK) {
        // ================= QUERY BLOCK: one b (fp32 codebook) =================
        const int b = bid;
        const float a0 = *qa0p, a1 = *qa1p, a2 = *qa2p;
        const float ind_a = *indap;

        if (tid < L) {
            int v = qbf[(size_t)b * L + tid];
            qidx[tid] = v;
            unsigned bal = __ballot_sync(0xffffffffu, v != PAD);
            if ((tid & 31) == 0) s_wcnt[tid >> 5] = __popc(bal);
        }
        __syncthreads();

        {
            const int c = tid;
            const int cnt = s_wcnt[0] + s_wcnt[1] + s_wcnt[2] + s_wcnt[3];
            float accA = 0.f, accB = 0.f;
            if (cnt == L) {
#pragma unroll 4
                for (int l4 = 0; l4 < 32; l4++) {
                    int4 v = ((const int4*)qidx)[l4];
                    float r0 = __ldg(cw + (size_t)v.x * H1 + c);
                    float r1 = __ldg(cw + (size_t)v.y * H1 + c);
                    float r2 = __ldg(cw + (size_t)v.z * H1 + c);
                    float r3 = __ldg(cw + (size_t)v.w * H1 + c);
                    accA += r0 + r1;
                    accB += r2 + r3;
                }
                qx[c] = prelu((accA + accB) * (1.f / (float)L), a0);
            } else {
#pragma unroll 4
                for (int l = 0; l < L; l++) {
                    int v = qidx[l];
                    float m = (v != PAD) ? 1.f : 0.f;
                    accA = fmaf(m, __ldg(cw + (size_t)v * H1 + c), accA);
                }
                float inv = cnt > 0 ? 1.f / (float)cnt : 0.f;
                qx[c] = prelu(accA * inv, a0);
            }
        }
        __syncthreads();

        {
            int j = tid & 63, dpp = tid >> 6;
            const float* w = qW1 + (size_t)(dpp * 64) * H2 + j;
            const float4* xq4 = (const float4*)(&qx[dpp * 64]);
            float acc = 0.f;
#pragma unroll 4
            for (int d4 = 0; d4 < 16; d4++) {
                float4 xv = xq4[d4];
                acc = fmaf(xv.x, __ldg(w + (d4 * 4 + 0) * H2), acc);
                acc = fmaf(xv.y, __ldg(w + (d4 * 4 + 1) * H2), acc);
                acc = fmaf(xv.z, __ldg(w + (d4 * 4 + 2) * H2), acc);
                acc = fmaf(xv.w, __ldg(w + (d4 * 4 + 3) * H2), acc);
            }
            qpart[dpp * 64 + j] = acc;
        }
        __syncthreads();
        if (tid < H2) {
            float acc = qb1[tid];
#pragma unroll
            for (int p = 0; p < 8; p++) acc += qpart[p * 64 + tid];
            qh1[tid] = prelu(acc, a1);
        }
        __syncthreads();
        if (tid < 256) {
            int j = tid & 63, dpp = tid >> 6;
            const float* w = qW2 + (size_t)(dpp * 16) * H2 + j;
            float acc = 0.f;
#pragma unroll
            for (int d = 0; d < 16; d++)
                acc = fmaf(qh1[dpp * 16 + d], __ldg(w + d * H2), acc);
            qpart[dpp * 64 + j] = acc;
        }
        __syncthreads();
        if (tid < H2) {
            float acc = qb2[tid] + qpart[tid] + qpart[64 + tid] +
                        qpart[128 + tid] + qpart[192 + tid];
            qh[tid] = prelu(acc, a2);
        }
        __syncthreads();

        if (tid < L) {
            int v = qidx[tid];
            float s = 0.f;
            if (v != PAD) {
                const float4* qr4 = (const float4*)(qew + (size_t)v * H2);
                const float4* qh4 = (const float4*)qh;
                float qd = 0.f;
#pragma unroll
                for (int h = 0; h < 16; h++) {
                    float4 r = __ldg(qr4 + h), q = qh4[h];
                    qd += r.x * q.x + r.y * q.y + r.z * q.z + r.w * q.w;
                }
                s = prelu(qd, ind_a) + 1.f;
            }
            __stcg(&g_qsw[b * L + tid], s);
        }
        __syncthreads();
        if (tid == 0) {
            __threadfence();
            atomicExch(&g_qflag[b], 1);
        }
    } else {
        // ================= POI BLOCK: 4 (b,k) pairs, fp16 gather =================
        const int pair0 = (bid - NQBLK) * BAGS;
        const int bb = pair0 >> 5;
        const float a0 = *pa0p, a1 = *pa1p, a2 = *pa2p;
        const float ind_a = *indap;

        {
            int v = pbf[(size_t)pair0 * L + tid];
            pidx[tid] = v;
            unsigned bal = __ballot_sync(0xffffffffu, v != PAD);
            if ((tid & 31) == 0) s_wcnt[tid >> 5] = __popc(bal);
        }
        if (tid < L) qidx[tid] = qbf[(size_t)bb * L + tid];
        {
            bitmap[tid] = 0u;
            bitmap[tid + 512] = 0u;
        }
        __syncthreads();

        // ---- gather: thread = (bag, 16B-chunk, row-half); LDG.128 + HADD2 ----
        const int g = tid >> 7;
        const int chunk = tid & 63;       // 8 halfs per chunk
        const int rh = (tid >> 6) & 1;    // row half
        {
            const int* ip = &pidx[g * L] + rh * 64;
            const uint4* cwh4 = (const uint4*)g_cwh;   // row = 64 uint4
            const int cnt = s_wcnt[g * 4] + s_wcnt[g * 4 + 1] +
                            s_wcnt[g * 4 + 2] + s_wcnt[g * 4 + 3];
            float acc[8];
#pragma unroll
            for (int i = 0; i < 8; i++) acc[i] = 0.f;
            if (cnt == L) {
#pragma unroll 4
                for (int p = 0; p < 32; p++) {
                    int2 v = ((const int2*)ip)[p];
                    uint4 u0 = __ldg(cwh4 + (size_t)v.x * 64 + chunk);
                    uint4 u1 = __ldg(cwh4 + (size_t)v.y * 64 + chunk);
                    __half2 h0 = __hadd2(*(const __half2*)&u0.x, *(const __half2*)&u1.x);
                    __half2 h1 = __hadd2(*(const __half2*)&u0.y, *(const __half2*)&u1.y);
                    __half2 h2 = __hadd2(*(const __half2*)&u0.z, *(const __half2*)&u1.z);
                    __half2 h3 = __hadd2(*(const __half2*)&u0.w, *(const __half2*)&u1.w);
                    float2 f0 = __half22float2(h0);
                    float2 f1 = __half22float2(h1);
                    float2 f2 = __half22float2(h2);
                    float2 f3 = __half22float2(h3);
                    acc[0] += f0.x; acc[1] += f0.y;
                    acc[2] += f1.x; acc[3] += f1.y;
                    acc[4] += f2.x; acc[5] += f2.y;
                    acc[6] += f3.x; acc[7] += f3.y;
                }
            } else {
                for (int l = 0; l < 64; l++) {
                    int v = ip[l];
                    float m = (v != PAD) ? 1.f : 0.f;
                    uint4 u = __ldg(cwh4 + (size_t)v * 64 + chunk);
                    float2 f0 = __half22float2(*(const __half2*)&u.x);
                    float2 f1 = __half22float2(*(const __half2*)&u.y);
                    float2 f2 = __half22float2(*(const __half2*)&u.z);
                    float2 f3 = __half22float2(*(const __half2*)&u.w);
                    acc[0] = fmaf(m, f0.x, acc[0]); acc[1] = fmaf(m, f0.y, acc[1]);
                    acc[2] = fmaf(m, f1.x, acc[2]); acc[3] = fmaf(m, f1.y, acc[3]);
                    acc[4] = fmaf(m, f2.x, acc[4]); acc[5] = fmaf(m, f2.y, acc[5]);
                    acc[6] = fmaf(m, f3.x, acc[6]); acc[7] = fmaf(m, f3.y, acc[7]);
                }
            }
            if (rh) {
                float* s = &mp[(g * 64 + chunk) * 8];
                *(float4*)s       = make_float4(acc[0], acc[1], acc[2], acc[3]);
                *(float4*)(s + 4) = make_float4(acc[4], acc[5], acc[6], acc[7]);
            }
            __syncthreads();
            if (!rh) {
                const float* s = &mp[(g * 64 + chunk) * 8];
                float inv = cnt > 0 ? 1.f / (float)cnt : 0.f;
                float4 o0, o1;
                o0.x = prelu((acc[0] + s[0]) * inv, a0);
                o0.y = prelu((acc[1] + s[1]) * inv, a0);
                o0.z = prelu((acc[2] + s[2]) * inv, a0);
                o0.w = prelu((acc[3] + s[3]) * inv, a0);
                o1.x = prelu((acc[4] + s[4]) * inv, a0);
                o1.y = prelu((acc[5] + s[5]) * inv, a0);
                o1.z = prelu((acc[6] + s[6]) * inv, a0);
                o1.w = prelu((acc[7] + s[7]) * inv, a0);
                *(float4*)(&x[g * XS + chunk * 8])     = o0;
                *(float4*)(&x[g * XS + chunk * 8 + 4]) = o1;
            }
        }
        __syncthreads();

        // ---- bitmap build (same phase as MLP1) ----
        {
            int v = pidx[tid];
            if (v != PAD)
                atomicOr(&bitmap[(tid >> 7) * 256 + (v >> 5)], 1u << (v & 31));
        }
        // ---- MLP1: fp16 d-pair W1, packed f32x2 FFMA2, 4 bag-accumulators ----
        {
            int j = tid & 63, dpp = tid >> 6;   // 8 d-parts of 64 (32 d-pairs)
            const __half2* w2p = g_w1h2 + (size_t)(dpp * 32) * H2 + j;
            const ulonglong2* x0 = (const ulonglong2*)(&x[0 * XS + dpp * 64]);
            const ulonglong2* x1 = (const ulonglong2*)(&x[1 * XS + dpp * 64]);
            const ulonglong2* x2 = (const ulonglong2*)(&x[2 * XS + dpp * 64]);
            const ulonglong2* x3 = (const ulonglong2*)(&x[3 * XS + dpp * 64]);
            ull a0q = 0, a1q = 0, a2q = 0, a3q = 0;
#pragma unroll 4
            for (int d4 = 0; d4 < 16; d4++) {
                float2 wlo = __half22float2(__ldg(w2p + (size_t)(d4 * 2) * H2));
                float2 whi = __half22float2(__ldg(w2p + (size_t)(d4 * 2 + 1) * H2));
                ull wA = pack_f2(wlo.x, wlo.y);
                ull wB = pack_f2(whi.x, whi.y);
                ulonglong2 xa = x0[d4], xb = x1[d4], xc = x2[d4], xd = x3[d4];
                ffma2(a0q, xa.x, wA); ffma2(a0q, xa.y, wB);
                ffma2(a1q, xb.x, wA); ffma2(a1q, xb.y, wB);
                ffma2(a2q, xc.x, wA); ffma2(a2q, xc.y, wB);
                ffma2(a3q, xd.x, wA); ffma2(a3q, xd.y, wB);
            }
            float2 u0 = unpack_f2(a0q), u1 = unpack_f2(a1q);
            float2 u2 = unpack_f2(a2q), u3 = unpack_f2(a3q);
            mp[dpp * 256 + j]       = u0.x + u0.y;
            mp[dpp * 256 + 64 + j]  = u1.x + u1.y;
            mp[dpp * 256 + 128 + j] = u2.x + u2.y;
            mp[dpp * 256 + 192 + j] = u3.x + u3.y;
        }
        __syncthreads();
        if (tid < 256) {
            int j = tid & 63, g2 = tid >> 6;
            float acc = pb1[j];
#pragma unroll
            for (int p = 0; p < 8; p++) acc += mp[p * 256 + g2 * 64 + j];
            h1s[g2 * HS + j] = prelu(acc, a1);
        }
        __syncthreads();
        // ---- MLP2: one W2 load feeds 4 bags; float4 LDS ----
        if (tid < 256) {
            int j = tid & 63, dpp = tid >> 6;   // 4 d-parts of 16
            const float* w = pW2 + (size_t)(dpp * 16) * H2 + j;
            const float4* h0 = (const float4*)(&h1s[0 * HS + dpp * 16]);
            const float4* h1 = (const float4*)(&h1s[1 * HS + dpp * 16]);
            const float4* h2 = (const float4*)(&h1s[2 * HS + dpp * 16]);
            const float4* h3 = (const float4*)(&h1s[3 * HS + dpp * 16]);
            float f0 = 0.f, f1 = 0.f, f2 = 0.f, f3 = 0.f;
#pragma unroll
            for (int d4 = 0; d4 < 4; d4++) {
                float4 a = h0[d4], bv = h1[d4], cv = h2[d4], dv = h3[d4];
#pragma unroll
                for (int u = 0; u < 4; u++) {
                    float wv = __ldg(w + (d4 * 4 + u) * H2);
                    f0 = fmaf((&a.x)[u], wv, f0);
                    f1 = fmaf((&bv.x)[u], wv, f1);
                    f2 = fmaf((&cv.x)[u], wv, f2);
                    f3 = fmaf((&dv.x)[u], wv, f3);
                }
            }
            mp[dpp * 256 + j]       = f0;
            mp[dpp * 256 + 64 + j]  = f1;
            mp[dpp * 256 + 128 + j] = f2;
            mp[dpp * 256 + 192 + j] = f3;
        }
        __syncthreads();
        if (tid < 256) {
            int j = tid & 63, g2 = tid >> 6;
            float acc = pb2[j] + mp[g2 * 64 + j] + mp[256 + g2 * 64 + j] +
                        mp[512 + g2 * 64 + j] + mp[768 + g2 * 64 + j];
            phs[g2 * HS + j] = prelu(acc, a2);
        }
        if (tid == 0) {
            while (((volatile int*)g_qflag)[bb] == 0) {}
            __threadfence();
        }
        __syncthreads();

        // ---- probe + p-side dot; qsw read direct from L2 ----
        {
            int gg = tid >> 7, i = tid & 127;
            int v = qidx[i];
            float val = 0.f;
            bool hit = (v != PAD) &&
                       ((bitmap[gg * 256 + (v >> 5)] >> (v & 31)) & 1u);
            float qs = __ldcg(&g_qsw[bb * L + i]);
            if (hit) {
                const float4* pr4 = (const float4*)(pew + (size_t)v * H2);
                const float4* ph4 = (const float4*)(&phs[gg * HS]);
                float pd = 0.f;
#pragma unroll
                for (int h = 0; h < 16; h++) {
                    float4 r = __ldg(pr4 + h), p = ph4[h];
                    pd += r.x * p.x + r.y * p.y + r.z * p.z + r.w * p.w;
                }
                val = qs * (prelu(pd, ind_a) + 1.f);
            }
#pragma unroll
            for (int off = 16; off > 0; off >>= 1)
                val += __shfl_xor_sync(0xffffffffu, val, off);
            if ((tid & 31) == 0) wpart[tid >> 5] = val;
        }
        __syncthreads();
        if (tid < BAGS) {
            float s = wpart[tid * 4] + wpart[tid * 4 + 1] +
                      wpart[tid * 4 + 2] + wpart[tid * 4 + 3];
            __stcg(&g_ts[pair0 + tid], s);
        }

        // ---- per-b distributed epilogue ----
        if (tid == 0) {
            __threadfence();
            s_is_last = (atomicAdd(&g_bcnt[bb], 1) == 7);
        }
        __syncthreads();
        if (s_is_last) {
            if (tid < K) {
                float ts = __ldcg(&g_ts[bb * K + tid]);
                float m = ts;
#pragma unroll
                for (int off = 16; off > 0; off >>= 1)
                    m = fmaxf(m, __shfl_xor_sync(0xffffffffu, m, off));
                float tsn = (2.f * ts - m) / (m + 1e-6f);
                float2 pl = __ldg((const float2*)(ploc + (size_t)(bb * K + tid) * 2));
                float dx = qloc[bb * 2]     - pl.x;
                float dy = qloc[bb * 2 + 1] - pl.y;
                float dist_sim = -logf(sqrtf(dx * dx + dy * dy) + 1.f);
                float A = *ap, Bc = *bp, C = *cp, D = *dp;
                float sig = 1.f / (1.f + expf(-(A * tsn + Bc)));
                out[bb * K + tid] = (C - sig) * (dist_sim - D);
            }
            if (tid == 0) {
                g_qflag[bb] = 0;
                __threadfence();
                atomicExch(&g_bcnt[bb], 0);
            }
        }
    }
}

// ---------------------------------------------------------------------------
extern "C" void kernel_launch(void* const* d_in, const int* in_sizes, int n_in,
                              void* d_out, int out_size) {
    const int*   qbf  = (const int*)d_in[0];
    const int*   pbf  = (const int*)d_in[1];
    const float* qloc = (const float*)d_in[2];
    const float* ploc = (const float*)d_in[3];
    const float* cw   = (const float*)d_in[4];
    const float* qW1  = (const float*)d_in[5];
    const float* qb1  = (const float*)d_in[6];
    const float* qW2  = (const float*)d_in[7];
    const float* qb2  = (const float*)d_in[8];
    const float* pW1  = (const float*)d_in[9];
    const float* pb1  = (const float*)d_in[10];
    const float* pW2  = (const float*)d_in[11];
    const float* pb2  = (const float*)d_in[12];
    const float* qew  = (const float*)d_in[13];
    const float* pew  = (const float*)d_in[14];
    const float* qa0  = (const float*)d_in[15];
    const float* qa1  = (const float*)d_in[16];
    const float* qa2  = (const float*)d_in[17];
    const float* pa0  = (const float*)d_in[18];
    const float* pa1  = (const float*)d_in[19];
    const float* pa2  = (const float*)d_in[20];
    const float* inda = (const float*)d_in[21];
    const float* a    = (const float*)d_in[22];
    const float* b    = (const float*)d_in[23];
    const float* c    = (const float*)d_in[24];
    const float* d    = (const float*)d_in[25];
    float* out = (float*)d_out;

    convert_kernel<<<256, 512>>>(cw, pW1);
    urban_kernel<<<NBLK, NT>>>(qbf, pbf, qloc, ploc, cw,
                               qW1, qb1, qW2, qb2,
                               pW1, pb1, pW2, pb2,
                               qew, pew,
                               qa0, qa1, qa2, pa0, pa1, pa2,
                               inda, a, b, c, d, out);
}